// round 4
// baseline (speedup 1.0000x reference)
#include <cuda_runtime.h>
#include <math.h>
#include <stdint.h>

// Problem constants
#define BB 2
#define TT 2048
#define CC 1024
#define HH 16
#define HS 64
#define MM (BB*TT)          // 4096 rows
#define EPS 1e-5f

// ---------------- scratch (device globals; no runtime allocation) ----------
__device__ float g_h   [MM*CC];        // LN output, tf32-rounded
__device__ float g_x1  [MM*CC];        // after attention residual (fp32)
__device__ float g_attn[MM*CC];        // attention output, tf32-rounded
__device__ float g_qkv [MM*3*CC];      // q|k|v, tf32-rounded
__device__ float g_wqkv[CC*3*CC];      // packed qkv weight, tf32-rounded
__device__ float g_bqkv[3*CC];
__device__ float g_mid [MM*4*CC];      // FFN hidden, tf32-rounded
__device__ float g_wor [CC*CC];        // Wo tf32-rounded
__device__ float g_w1r [CC*4*CC];      // W1 tf32-rounded
__device__ float g_w2r [4*CC*CC];      // W2 tf32-rounded
__device__ float g_mean[BB*CC];
__device__ float g_inv [BB*CC];

// ---------------- helpers ---------------------------------------------------
__device__ __forceinline__ uint32_t f2tf32(float f) {
    uint32_t r;
    asm("cvt.rna.tf32.f32 %0, %1;" : "=r"(r) : "f"(f));
    return r;
}
__device__ __forceinline__ float rtf(float f) { return __uint_as_float(f2tf32(f)); }

__device__ __forceinline__ void mma_tf32(float c[4], const uint32_t a[4],
                                         uint32_t b0, uint32_t b1) {
    asm("mma.sync.aligned.m16n8k8.row.col.f32.tf32.tf32.f32 "
        "{%0,%1,%2,%3},{%4,%5,%6,%7},{%8,%9},{%0,%1,%2,%3};"
        : "+f"(c[0]), "+f"(c[1]), "+f"(c[2]), "+f"(c[3])
        : "r"(a[0]), "r"(a[1]), "r"(a[2]), "r"(a[3]), "r"(b0), "r"(b1));
}

__device__ __forceinline__ void cp16(void* smem, const void* gmem) {
    uint32_t s = (uint32_t)__cvta_generic_to_shared(smem);
    asm volatile("cp.async.cg.shared.global [%0], [%1], 16;\n" :: "r"(s), "l"(gmem));
}
__device__ __forceinline__ void cp_commit() {
    asm volatile("cp.async.commit_group;\n");
}
template<int N>
__device__ __forceinline__ void cp_wait() {
    asm volatile("cp.async.wait_group %0;\n" :: "n"(N));
}

// ---------------- LayerNorm over axis=1 (sequence axis) --------------------
__global__ void ln_stats(const float* __restrict__ x,
                         float* __restrict__ mean, float* __restrict__ inv)
{
    int c = blockIdx.x * 32 + threadIdx.x;
    int b = blockIdx.y;
    float s = 0.f, ss = 0.f;
    for (int t = threadIdx.y; t < TT; t += 8) {
        float v = x[((size_t)b*TT + t)*CC + c];
        s += v; ss += v*v;
    }
    __shared__ float sh_s[8][32];
    __shared__ float sh_q[8][32];
    sh_s[threadIdx.y][threadIdx.x] = s;
    sh_q[threadIdx.y][threadIdx.x] = ss;
    __syncthreads();
    if (threadIdx.y == 0) {
        #pragma unroll
        for (int i = 1; i < 8; i++) { s += sh_s[i][threadIdx.x]; ss += sh_q[i][threadIdx.x]; }
        float mu  = s / (float)TT;
        float var = (ss - s*mu) / (float)(TT - 1);
        mean[b*CC + c] = mu;
        inv [b*CC + c] = 1.f / (sqrtf(var) + EPS);
    }
}

// writes tf32-rounded output (only ever consumed as a GEMM A operand)
__global__ void ln_apply(const float* __restrict__ x,
                         const float* __restrict__ mean, const float* __restrict__ inv,
                         const float* __restrict__ gamma, const float* __restrict__ beta,
                         float* __restrict__ y)
{
    int idx = blockIdx.x * blockDim.x + threadIdx.x;
    if (idx >= MM*CC) return;
    int c  = idx & (CC-1);
    int bt = idx >> 10;
    int b  = bt >> 11;
    y[idx] = rtf(gamma[c] * ((x[idx] - mean[b*CC + c]) * inv[b*CC + c]) + beta[c]);
}

// ---------------- round a weight matrix to tf32 bits ------------------------
__global__ void round_tf32(const float* __restrict__ src, float* __restrict__ dst, int n)
{
    for (int i = blockIdx.x * blockDim.x + threadIdx.x; i < n; i += gridDim.x * blockDim.x)
        dst[i] = rtf(src[i]);
}

// ---------------- pack Wq/Wk/Wv [H,C,HS] -> [C, 3C], tf32-rounded ----------
__global__ void pack_qkv(const float* __restrict__ Wq, const float* __restrict__ Wk,
                         const float* __restrict__ Wv,
                         const float* __restrict__ bq, const float* __restrict__ bk,
                         const float* __restrict__ bv,
                         float* __restrict__ W, float* __restrict__ bias)
{
    const int total = CC * 3 * CC;
    for (int idx = blockIdx.x * blockDim.x + threadIdx.x; idx < total;
         idx += gridDim.x * blockDim.x) {
        int k  = idx / (3*CC);
        int nn = idx % (3*CC);
        int sel = nn / CC;
        int r   = nn % CC;
        int h = r / HS, d = r % HS;
        const float* src = (sel == 0) ? Wq : (sel == 1) ? Wk : Wv;
        W[idx] = rtf(src[((size_t)h*CC + k)*HS + d]);
        if (idx < 3*CC) {
            const float* bs = (idx < CC) ? bq : (idx < 2*CC) ? bk : bv;
            bias[idx] = bs[idx % CC];
        }
    }
}

// ---------------- TF32 MMA GEMM, BK=32, 3-stage cp.async -------------------
// 128x128 block tile, 8 warps (warp tile 32x64), operands pre-rounded to tf32.
template<bool RELU, bool RES, bool ROUND>
__global__ void __launch_bounds__(256, 2) mma_gemm(
    const float* __restrict__ A, const float* __restrict__ Bm,
    const float* __restrict__ bias, const float* __restrict__ Rm,
    float* __restrict__ Cm, int M, int N, int K)
{
    __shared__ float As[3][128][36];    // [stage][m][k], stride 36: conflict-free
    __shared__ float Bs[3][32][136];    // [stage][k][n], stride 136: conflict-free

    const int tid  = threadIdx.x;
    const int lane = tid & 31;
    const int warp = tid >> 5;
    const int wm = warp & 3;
    const int wn = warp >> 2;
    const int r = lane >> 2;
    const int c = lane & 3;
    const int rowBase = blockIdx.y * 128;
    const int colBase = blockIdx.x * 128;

    float acc[2][8][4];
    #pragma unroll
    for (int mt = 0; mt < 2; mt++)
        #pragma unroll
        for (int nt = 0; nt < 8; nt++)
            #pragma unroll
            for (int i = 0; i < 4; i++) acc[mt][nt][i] = 0.f;

    const float* Ag = A + (size_t)rowBase * K;
    const float* Bg = Bm + colBase;

    auto stage = [&](int s, int k0) {
        #pragma unroll
        for (int p = 0; p < 4; p++) {
            int q = tid + p*256;
            int row = q >> 3, kc = (q & 7) * 4;
            cp16(&As[s][row][kc], Ag + (size_t)row * K + k0 + kc);
        }
        #pragma unroll
        for (int p = 0; p < 4; p++) {
            int q = tid + p*256;
            int kr = q >> 5, nc = (q & 31) * 4;
            cp16(&Bs[s][kr][nc], Bg + (size_t)(k0 + kr) * N + nc);
        }
        cp_commit();
    };

    const int nIter = K >> 5;
    stage(0, 0);
    stage(1, 32);
    int sc = 0, sn = 1, sf = 2;

    for (int it = 0; it < nIter; it++) {
        if (it + 1 < nIter) cp_wait<1>(); else cp_wait<0>();
        __syncthreads();
        if (it + 2 < nIter) stage(sf, (it + 2) << 5);

        #pragma unroll
        for (int ks = 0; ks < 32; ks += 8) {
            uint32_t af0[4], af1[4];
            const int m0 = wm*32, m1 = wm*32 + 16;
            af0[0] = __float_as_uint(As[sc][m0+r  ][ks+c  ]);
            af0[1] = __float_as_uint(As[sc][m0+r+8][ks+c  ]);
            af0[2] = __float_as_uint(As[sc][m0+r  ][ks+c+4]);
            af0[3] = __float_as_uint(As[sc][m0+r+8][ks+c+4]);
            af1[0] = __float_as_uint(As[sc][m1+r  ][ks+c  ]);
            af1[1] = __float_as_uint(As[sc][m1+r+8][ks+c  ]);
            af1[2] = __float_as_uint(As[sc][m1+r  ][ks+c+4]);
            af1[3] = __float_as_uint(As[sc][m1+r+8][ks+c+4]);
            #pragma unroll
            for (int nt = 0; nt < 8; nt++) {
                int n = wn*64 + nt*8;
                uint32_t b0 = __float_as_uint(Bs[sc][ks+c  ][n+r]);
                uint32_t b1 = __float_as_uint(Bs[sc][ks+c+4][n+r]);
                mma_tf32(acc[0][nt], af0, b0, b1);
                mma_tf32(acc[1][nt], af1, b0, b1);
            }
        }
        int t = sc; sc = sn; sn = sf; sf = t;
    }

    // epilogue
    #pragma unroll
    for (int mt = 0; mt < 2; mt++) {
        #pragma unroll
        for (int nt = 0; nt < 8; nt++) {
            int row0 = rowBase + wm*32 + mt*16 + r;
            int col  = colBase + wn*64 + nt*8 + 2*c;
            float bi0 = bias[col], bi1 = bias[col+1];
            float v0 = acc[mt][nt][0] + bi0;
            float v1 = acc[mt][nt][1] + bi1;
            float v2 = acc[mt][nt][2] + bi0;
            float v3 = acc[mt][nt][3] + bi1;
            if (RELU) { v0=fmaxf(v0,0.f); v1=fmaxf(v1,0.f); v2=fmaxf(v2,0.f); v3=fmaxf(v3,0.f); }
            if (RES) {
                const float2 r0 = *(const float2*)(Rm + (size_t)row0*N + col);
                const float2 r1 = *(const float2*)(Rm + (size_t)(row0+8)*N + col);
                v0 += r0.x; v1 += r0.y; v2 += r1.x; v3 += r1.y;
            }
            if (ROUND) { v0 = rtf(v0); v1 = rtf(v1); v2 = rtf(v2); v3 = rtf(v3); }
            *(float2*)(Cm + (size_t)row0*N + col)     = make_float2(v0, v1);
            *(float2*)(Cm + (size_t)(row0+8)*N + col) = make_float2(v2, v3);
        }
    }
}

// ---------------- flash attention (tf32 MMA, non-causal) -------------------
// q-tile 128 (8 warps), key-tile 64. K double-buffered cp.async, V single
// buffer with its wait deferred past softmax. qkv is pre-rounded to tf32.
__global__ void __launch_bounds__(256, 2) flash_mma(const float* __restrict__ qkv,
                                                    float* __restrict__ out)
{
    __shared__ float Ks[2][64][76];   // [buf][key][d], stride 76: conflict-free col reads
    __shared__ float Vs[64][72];      // [key][d],     stride 72: conflict-free row reads
    __shared__ uint32_t Ps[128][72];  // [qrow][key]

    const int tid  = threadIdx.x;
    const int lane = tid & 31;
    const int warp = tid >> 5;        // 0..7
    const int r = lane >> 2;
    const int c = lane & 3;
    const int b = blockIdx.z, h = blockIdx.y;
    const int q0 = blockIdx.x * 128;
    const float scale = 0.125f;       // exact power of two: preserves tf32 bits

    // Q fragments (already tf32-rounded in gmem)
    uint32_t qf[8][4];
    {
        const float* qp  = qkv + (size_t)(b*TT + q0 + warp*16 + r) * (3*CC) + h*HS;
        const float* qp8 = qp + (size_t)8 * (3*CC);
        #pragma unroll
        for (int ks = 0; ks < 8; ks++) {
            qf[ks][0] = __float_as_uint(qp [ks*8 + c    ] * scale);
            qf[ks][1] = __float_as_uint(qp8[ks*8 + c    ] * scale);
            qf[ks][2] = __float_as_uint(qp [ks*8 + c + 4] * scale);
            qf[ks][3] = __float_as_uint(qp8[ks*8 + c + 4] * scale);
        }
    }

    float oacc[8][4];
    #pragma unroll
    for (int nt = 0; nt < 8; nt++)
        #pragma unroll
        for (int i = 0; i < 4; i++) oacc[nt][i] = 0.f;
    float m0 = -1e30f, m1 = -1e30f, l0 = 0.f, l1 = 0.f;

    auto stageK = [&](int buf, int s0) {
        #pragma unroll
        for (int p = 0; p < 4; p++) {
            int q = tid + p*256;
            int row = q >> 4, dc = (q & 15) * 4;
            cp16(&Ks[buf][row][dc],
                 qkv + (size_t)(b*TT + s0 + row)*(3*CC) + CC + h*HS + dc);
        }
        cp_commit();
    };
    auto stageV = [&](int s0) {
        #pragma unroll
        for (int p = 0; p < 4; p++) {
            int q = tid + p*256;
            int row = q >> 4, dc = (q & 15) * 4;
            cp16(&Vs[row][dc],
                 qkv + (size_t)(b*TT + s0 + row)*(3*CC) + 2*CC + h*HS + dc);
        }
        cp_commit();
    };

    const int nIter = TT / 64;
    stageK(0, 0);

    for (int i = 0; i < nIter; i++) {
        const int s0 = i * 64;
        const int kb = i & 1;
        cp_wait<0>();            // K(i) ready (V(i-1) already consumed)
        __syncthreads();
        stageV(s0);              // V for THIS tile: latency hidden by S+softmax
        if (i + 1 < nIter) stageK(kb ^ 1, s0 + 64);

        // S = Q K^T
        float sa[8][4];
        #pragma unroll
        for (int nt = 0; nt < 8; nt++)
            #pragma unroll
            for (int j = 0; j < 4; j++) sa[nt][j] = 0.f;
        #pragma unroll
        for (int ks = 0; ks < 8; ks++) {
            #pragma unroll
            for (int nt = 0; nt < 8; nt++) {
                uint32_t b0 = __float_as_uint(Ks[kb][nt*8+r][ks*8+c  ]);
                uint32_t b1 = __float_as_uint(Ks[kb][nt*8+r][ks*8+c+4]);
                mma_tf32(sa[nt], qf[ks], b0, b1);
            }
        }

        // online softmax
        float mx0 = -1e30f, mx1 = -1e30f;
        #pragma unroll
        for (int nt = 0; nt < 8; nt++) {
            mx0 = fmaxf(mx0, fmaxf(sa[nt][0], sa[nt][1]));
            mx1 = fmaxf(mx1, fmaxf(sa[nt][2], sa[nt][3]));
        }
        mx0 = fmaxf(mx0, __shfl_xor_sync(0xffffffff, mx0, 1));
        mx0 = fmaxf(mx0, __shfl_xor_sync(0xffffffff, mx0, 2));
        mx1 = fmaxf(mx1, __shfl_xor_sync(0xffffffff, mx1, 1));
        mx1 = fmaxf(mx1, __shfl_xor_sync(0xffffffff, mx1, 2));
        float mn0 = fmaxf(m0, mx0), mn1 = fmaxf(m1, mx1);
        float f0 = __expf(m0 - mn0), f1 = __expf(m1 - mn1);
        m0 = mn0; m1 = mn1;

        float ps0 = 0.f, ps1 = 0.f;
        const int prow = warp*16 + r;
        #pragma unroll
        for (int nt = 0; nt < 8; nt++) {
            float p0 = __expf(sa[nt][0] - mn0);
            float p1 = __expf(sa[nt][1] - mn0);
            float p2 = __expf(sa[nt][2] - mn1);
            float p3 = __expf(sa[nt][3] - mn1);
            ps0 += p0 + p1; ps1 += p2 + p3;
            uint2 w0; w0.x = f2tf32(p0); w0.y = f2tf32(p1);
            uint2 w1; w1.x = f2tf32(p2); w1.y = f2tf32(p3);
            *(uint2*)&Ps[prow    ][nt*8 + 2*c] = w0;
            *(uint2*)&Ps[prow + 8][nt*8 + 2*c] = w1;
        }
        ps0 += __shfl_xor_sync(0xffffffff, ps0, 1);
        ps0 += __shfl_xor_sync(0xffffffff, ps0, 2);
        ps1 += __shfl_xor_sync(0xffffffff, ps1, 1);
        ps1 += __shfl_xor_sync(0xffffffff, ps1, 2);
        l0 = l0 * f0 + ps0;
        l1 = l1 * f1 + ps1;

        #pragma unroll
        for (int nt = 0; nt < 8; nt++) {
            oacc[nt][0] *= f0; oacc[nt][1] *= f0;
            oacc[nt][2] *= f1; oacc[nt][3] *= f1;
        }

        // V must be resident; K(i+1) may still be in flight
        if (i + 1 < nIter) cp_wait<1>(); else cp_wait<0>();
        __syncthreads();

        // O += P V
        #pragma unroll
        for (int ks = 0; ks < 8; ks++) {
            uint32_t af[4];
            af[0] = Ps[prow    ][ks*8 + c    ];
            af[1] = Ps[prow + 8][ks*8 + c    ];
            af[2] = Ps[prow    ][ks*8 + c + 4];
            af[3] = Ps[prow + 8][ks*8 + c + 4];
            #pragma unroll
            for (int nt = 0; nt < 8; nt++) {
                uint32_t b0 = __float_as_uint(Vs[ks*8+c  ][nt*8+r]);
                uint32_t b1 = __float_as_uint(Vs[ks*8+c+4][nt*8+r]);
                mma_tf32(oacc[nt], af, b0, b1);
            }
        }
    }

    // write out, tf32-rounded (consumed only as O-proj GEMM A operand)
    float il0 = 1.f / l0, il1 = 1.f / l1;
    const int grow = b*TT + q0 + warp*16 + r;
    float* op0 = out + (size_t)grow * CC + h*HS;
    float* op1 = op0 + (size_t)8 * CC;
    #pragma unroll
    for (int nt = 0; nt < 8; nt++) {
        int col = nt*8 + 2*c;
        *(float2*)(op0 + col) = make_float2(rtf(oacc[nt][0]*il0), rtf(oacc[nt][1]*il0));
        *(float2*)(op1 + col) = make_float2(rtf(oacc[nt][2]*il1), rtf(oacc[nt][3]*il1));
    }
}

// ---------------- launch -----------------------------------------------
extern "C" void kernel_launch(void* const* d_in, const int* in_sizes, int n_in,
                              void* d_out, int out_size)
{
    const float* x      = (const float*)d_in[0];
    const float* Wq     = (const float*)d_in[1];
    const float* bq     = (const float*)d_in[2];
    const float* Wk     = (const float*)d_in[3];
    const float* bk     = (const float*)d_in[4];
    const float* Wv     = (const float*)d_in[5];
    const float* bv     = (const float*)d_in[6];
    const float* Wo     = (const float*)d_in[7];
    const float* bo     = (const float*)d_in[8];
    const float* W1     = (const float*)d_in[9];
    const float* b1     = (const float*)d_in[10];
    const float* W2     = (const float*)d_in[11];
    const float* b2     = (const float*)d_in[12];
    const float* gamma1 = (const float*)d_in[13];
    const float* beta1  = (const float*)d_in[14];
    const float* gamma2 = (const float*)d_in[15];
    const float* beta2  = (const float*)d_in[16];
    float* out = (float*)d_out;

    float *p_h, *p_x1, *p_attn, *p_qkv, *p_wqkv, *p_bqkv, *p_mid, *p_mean, *p_inv;
    float *p_wor, *p_w1r, *p_w2r;
    cudaGetSymbolAddress((void**)&p_h,    g_h);
    cudaGetSymbolAddress((void**)&p_x1,   g_x1);
    cudaGetSymbolAddress((void**)&p_attn, g_attn);
    cudaGetSymbolAddress((void**)&p_qkv,  g_qkv);
    cudaGetSymbolAddress((void**)&p_wqkv, g_wqkv);
    cudaGetSymbolAddress((void**)&p_bqkv, g_bqkv);
    cudaGetSymbolAddress((void**)&p_mid,  g_mid);
    cudaGetSymbolAddress((void**)&p_mean, g_mean);
    cudaGetSymbolAddress((void**)&p_inv,  g_inv);
    cudaGetSymbolAddress((void**)&p_wor,  g_wor);
    cudaGetSymbolAddress((void**)&p_w1r,  g_w1r);
    cudaGetSymbolAddress((void**)&p_w2r,  g_w2r);

    dim3 lnb(32, 8);
    dim3 lng(CC/32, BB);
    const int elemBlocks = (MM*CC + 255)/256;

    // 0) pre-round weights to tf32 bits
    round_tf32<<<1024, 256>>>(Wo, p_wor, CC*CC);
    round_tf32<<<2048, 256>>>(W1, p_w1r, CC*4*CC);
    round_tf32<<<2048, 256>>>(W2, p_w2r, 4*CC*CC);
    pack_qkv<<<4096, 256>>>(Wq, Wk, Wv, bq, bk, bv, p_wqkv, p_bqkv);

    // 1) LN1 (rounded output)
    ln_stats<<<lng, lnb>>>(x, p_mean, p_inv);
    ln_apply<<<elemBlocks, 256>>>(x, p_mean, p_inv, gamma1, beta1, p_h);

    // 2) fused QKV GEMM -> g_qkv (rounded)
    mma_gemm<false,false,true><<<dim3(3*CC/128, MM/128), 256>>>(p_h, p_wqkv, p_bqkv, nullptr,
                                                                p_qkv, MM, 3*CC, CC);

    // 3) flash attention -> g_attn (rounded)
    flash_mma<<<dim3(TT/128, HH, BB), 256>>>(p_qkv, p_attn);

    // 4) output projection + residual -> g_x1 (fp32)
    mma_gemm<false,true,false><<<dim3(CC/128, MM/128), 256>>>(p_attn, p_wor, bo, x,
                                                              p_x1, MM, CC, CC);

    // 5) LN2 (rounded output)
    ln_stats<<<lng, lnb>>>(p_x1, p_mean, p_inv);
    ln_apply<<<elemBlocks, 256>>>(p_x1, p_mean, p_inv, gamma2, beta2, p_h);

    // 6) FFN
    mma_gemm<true,false,true><<<dim3(4*CC/128, MM/128), 256>>>(p_h, p_w1r, b1, nullptr,
                                                               p_mid, MM, 4*CC, CC);
    mma_gemm<false,true,false><<<dim3(CC/128, MM/128), 256>>>(p_mid, p_w2r, b2, p_x1,
                                                              out, MM, CC, 4*CC);
}

// round 5
// speedup vs baseline: 1.1984x; 1.1984x over previous
#include <cuda_runtime.h>
#include <math.h>
#include <stdint.h>

// Problem constants
#define BB 2
#define TT 2048
#define CC 1024
#define HH 16
#define HS 64
#define MM (BB*TT)          // 4096 rows
#define EPS 1e-5f

// ---------------- scratch (device globals; no runtime allocation) ----------
__device__ float g_h   [MM*CC];        // LN output, tf32-rounded
__device__ float g_x1  [MM*CC];        // after attention residual (fp32)
__device__ float g_attn[MM*CC];        // attention output, tf32-rounded
__device__ float g_qkv [MM*3*CC];      // q|k|v, tf32-rounded
__device__ float g_wqkv[CC*3*CC];      // packed qkv weight, tf32-rounded
__device__ float g_bqkv[3*CC];
__device__ float g_mid [MM*4*CC];      // FFN hidden, tf32-rounded
__device__ float g_mean[BB*CC];
__device__ float g_inv [BB*CC];

// ---------------- helpers ---------------------------------------------------
__device__ __forceinline__ uint32_t f2tf32(float f) {
    uint32_t r;
    asm("cvt.rna.tf32.f32 %0, %1;" : "=r"(r) : "f"(f));
    return r;
}
__device__ __forceinline__ float rtf(float f) { return __uint_as_float(f2tf32(f)); }

__device__ __forceinline__ void mma_tf32(float c[4], const uint32_t a[4],
                                         uint32_t b0, uint32_t b1) {
    asm("mma.sync.aligned.m16n8k8.row.col.f32.tf32.tf32.f32 "
        "{%0,%1,%2,%3},{%4,%5,%6,%7},{%8,%9},{%0,%1,%2,%3};"
        : "+f"(c[0]), "+f"(c[1]), "+f"(c[2]), "+f"(c[3])
        : "r"(a[0]), "r"(a[1]), "r"(a[2]), "r"(a[3]), "r"(b0), "r"(b1));
}

__device__ __forceinline__ void cp16(void* smem, const void* gmem) {
    uint32_t s = (uint32_t)__cvta_generic_to_shared(smem);
    asm volatile("cp.async.cg.shared.global [%0], [%1], 16;\n" :: "r"(s), "l"(gmem));
}
__device__ __forceinline__ void cp_commit() {
    asm volatile("cp.async.commit_group;\n");
}
template<int N>
__device__ __forceinline__ void cp_wait() {
    asm volatile("cp.async.wait_group %0;\n" :: "n"(N));
}

// ---------------- LayerNorm over axis=1 (sequence axis) --------------------
__global__ void ln_stats(const float* __restrict__ x,
                         float* __restrict__ mean, float* __restrict__ inv)
{
    int c = blockIdx.x * 32 + threadIdx.x;
    int b = blockIdx.y;
    float s = 0.f, ss = 0.f;
    for (int t = threadIdx.y; t < TT; t += 8) {
        float v = x[((size_t)b*TT + t)*CC + c];
        s += v; ss += v*v;
    }
    __shared__ float sh_s[8][32];
    __shared__ float sh_q[8][32];
    sh_s[threadIdx.y][threadIdx.x] = s;
    sh_q[threadIdx.y][threadIdx.x] = ss;
    __syncthreads();
    if (threadIdx.y == 0) {
        #pragma unroll
        for (int i = 1; i < 8; i++) { s += sh_s[i][threadIdx.x]; ss += sh_q[i][threadIdx.x]; }
        float mu  = s / (float)TT;
        float var = (ss - s*mu) / (float)(TT - 1);
        mean[b*CC + c] = mu;
        inv [b*CC + c] = 1.f / (sqrtf(var) + EPS);
    }
}

// writes tf32-rounded output (only consumed as a GEMM A operand)
__global__ void ln_apply(const float* __restrict__ x,
                         const float* __restrict__ mean, const float* __restrict__ inv,
                         const float* __restrict__ gamma, const float* __restrict__ beta,
                         float* __restrict__ y)
{
    int idx = blockIdx.x * blockDim.x + threadIdx.x;
    if (idx >= MM*CC) return;
    int c  = idx & (CC-1);
    int bt = idx >> 10;
    int b  = bt >> 11;
    y[idx] = rtf(gamma[c] * ((x[idx] - mean[b*CC + c]) * inv[b*CC + c]) + beta[c]);
}

// ---------------- pack Wq/Wk/Wv [H,C,HS] -> [C, 3C], tf32-rounded ----------
__global__ void pack_qkv(const float* __restrict__ Wq, const float* __restrict__ Wk,
                         const float* __restrict__ Wv,
                         const float* __restrict__ bq, const float* __restrict__ bk,
                         const float* __restrict__ bv,
                         float* __restrict__ W, float* __restrict__ bias)
{
    const int total = CC * 3 * CC;
    for (int idx = blockIdx.x * blockDim.x + threadIdx.x; idx < total;
         idx += gridDim.x * blockDim.x) {
        int k  = idx / (3*CC);
        int nn = idx % (3*CC);
        int sel = nn / CC;
        int r   = nn % CC;
        int h = r / HS, d = r % HS;
        const float* src = (sel == 0) ? Wq : (sel == 1) ? Wk : Wv;
        W[idx] = rtf(src[((size_t)h*CC + k)*HS + d]);
        if (idx < 3*CC) {
            const float* bs = (idx < CC) ? bq : (idx < 2*CC) ? bk : bv;
            bias[idx] = bs[idx % CC];
        }
    }
}

// ---------------- TF32 MMA GEMM, 2-stage cp.async pipeline (R3 structure) --
// 128x128 block tile, BK=16, 8 warps (warp tile 32x64), m16n8k8 tf32 MMA.
// A operand ALWAYS pre-rounded to tf32 bits. B cvt only when BCVT.
template<bool RELU, bool RES, bool ROUND, bool BCVT>
__global__ void __launch_bounds__(256, 2) mma_gemm(
    const float* __restrict__ A, const float* __restrict__ Bm,
    const float* __restrict__ bias, const float* __restrict__ Rm,
    float* __restrict__ Cm, int M, int N, int K)
{
    __shared__ float As[2][128][20];    // [stage][m][k], stride 20: conflict-free
    __shared__ float Bs[2][16][136];    // [stage][k][n], stride 136: conflict-free

    const int tid  = threadIdx.x;
    const int lane = tid & 31;
    const int warp = tid >> 5;
    const int wm = warp & 3;
    const int wn = warp >> 2;
    const int r = lane >> 2;
    const int c = lane & 3;
    const int rowBase = blockIdx.y * 128;
    const int colBase = blockIdx.x * 128;

    float acc[2][8][4];
    #pragma unroll
    for (int mt = 0; mt < 2; mt++)
        #pragma unroll
        for (int nt = 0; nt < 8; nt++)
            #pragma unroll
            for (int i = 0; i < 4; i++) acc[mt][nt][i] = 0.f;

    const float* Ag = A + (size_t)rowBase * K;
    const float* Bg = Bm + colBase;

    auto stage = [&](int s, int k0) {
        #pragma unroll
        for (int p = 0; p < 2; p++) {
            int q = tid + p*256;
            int row = q >> 2, kc = (q & 3) * 4;
            cp16(&As[s][row][kc], Ag + (size_t)row * K + k0 + kc);
        }
        #pragma unroll
        for (int p = 0; p < 2; p++) {
            int q = tid + p*256;
            int kr = q >> 5, nc = (q & 31) * 4;
            cp16(&Bs[s][kr][nc], Bg + (size_t)(k0 + kr) * N + nc);
        }
        cp_commit();
    };

    const int nIter = K >> 4;
    stage(0, 0);

    for (int it = 0; it < nIter; it++) {
        const int s = it & 1;
        if (it + 1 < nIter) {
            stage(s ^ 1, (it + 1) << 4);
            cp_wait<1>();
        } else {
            cp_wait<0>();
        }
        __syncthreads();

        #pragma unroll
        for (int ks = 0; ks < 16; ks += 8) {
            uint32_t af0[4], af1[4];
            const int m0 = wm*32, m1 = wm*32 + 16;
            af0[0] = __float_as_uint(As[s][m0+r  ][ks+c  ]);
            af0[1] = __float_as_uint(As[s][m0+r+8][ks+c  ]);
            af0[2] = __float_as_uint(As[s][m0+r  ][ks+c+4]);
            af0[3] = __float_as_uint(As[s][m0+r+8][ks+c+4]);
            af1[0] = __float_as_uint(As[s][m1+r  ][ks+c  ]);
            af1[1] = __float_as_uint(As[s][m1+r+8][ks+c  ]);
            af1[2] = __float_as_uint(As[s][m1+r  ][ks+c+4]);
            af1[3] = __float_as_uint(As[s][m1+r+8][ks+c+4]);
            #pragma unroll
            for (int nt = 0; nt < 8; nt++) {
                int n = wn*64 + nt*8;
                uint32_t b0, b1;
                if (BCVT) {
                    b0 = f2tf32(Bs[s][ks+c  ][n+r]);
                    b1 = f2tf32(Bs[s][ks+c+4][n+r]);
                } else {
                    b0 = __float_as_uint(Bs[s][ks+c  ][n+r]);
                    b1 = __float_as_uint(Bs[s][ks+c+4][n+r]);
                }
                mma_tf32(acc[0][nt], af0, b0, b1);
                mma_tf32(acc[1][nt], af1, b0, b1);
            }
        }
        __syncthreads();
    }

    // epilogue
    #pragma unroll
    for (int mt = 0; mt < 2; mt++) {
        #pragma unroll
        for (int nt = 0; nt < 8; nt++) {
            int row0 = rowBase + wm*32 + mt*16 + r;
            int col  = colBase + wn*64 + nt*8 + 2*c;
            float bi0 = bias[col], bi1 = bias[col+1];
            float v0 = acc[mt][nt][0] + bi0;
            float v1 = acc[mt][nt][1] + bi1;
            float v2 = acc[mt][nt][2] + bi0;
            float v3 = acc[mt][nt][3] + bi1;
            if (RELU) { v0=fmaxf(v0,0.f); v1=fmaxf(v1,0.f); v2=fmaxf(v2,0.f); v3=fmaxf(v3,0.f); }
            if (RES) {
                const float2 r0 = *(const float2*)(Rm + (size_t)row0*N + col);
                const float2 r1 = *(const float2*)(Rm + (size_t)(row0+8)*N + col);
                v0 += r0.x; v1 += r0.y; v2 += r1.x; v3 += r1.y;
            }
            if (ROUND) { v0 = rtf(v0); v1 = rtf(v1); v2 = rtf(v2); v3 = rtf(v3); }
            *(float2*)(Cm + (size_t)row0*N + col)     = make_float2(v0, v1);
            *(float2*)(Cm + (size_t)(row0+8)*N + col) = make_float2(v2, v3);
        }
    }
}

// ---------------- flash attention (tf32 MMA, non-causal, R3 structure) -----
// grid (T/64, H, B); 128 threads = 4 warps; each warp owns 16 query rows.
// qkv is pre-rounded to tf32 bits -> no cvt at staging or Q load.
__global__ void __launch_bounds__(128) flash_mma(const float* __restrict__ qkv,
                                                 float* __restrict__ out)
{
    __shared__ uint32_t Kt[64][72];   // [d][key]  (K transposed)
    __shared__ uint32_t Vs[64][72];   // [key][d]
    __shared__ uint32_t Ps[64][72];   // [qrow][key]

    const int tid  = threadIdx.x;
    const int lane = tid & 31;
    const int warp = tid >> 5;
    const int r = lane >> 2;
    const int c = lane & 3;
    const int b = blockIdx.z, h = blockIdx.y;
    const int q0 = blockIdx.x * 64;
    const float scale = 0.125f;       // exact power of two: preserves tf32 bits

    uint32_t qf[8][4];
    {
        const int qr0 = b*TT + q0 + warp*16 + r;
        const float* qp = qkv + (size_t)qr0 * (3*CC) + h*HS;
        const float* qp8 = qp + (size_t)8 * (3*CC);
        #pragma unroll
        for (int ks = 0; ks < 8; ks++) {
            qf[ks][0] = __float_as_uint(qp [ks*8 + c    ] * scale);
            qf[ks][1] = __float_as_uint(qp8[ks*8 + c    ] * scale);
            qf[ks][2] = __float_as_uint(qp [ks*8 + c + 4] * scale);
            qf[ks][3] = __float_as_uint(qp8[ks*8 + c + 4] * scale);
        }
    }

    float oacc[8][4];
    #pragma unroll
    for (int nt = 0; nt < 8; nt++)
        #pragma unroll
        for (int i = 0; i < 4; i++) oacc[nt][i] = 0.f;
    float m0 = -1e30f, m1 = -1e30f, l0 = 0.f, l1 = 0.f;

    const int skey = tid >> 1;
    const int sdg  = (tid & 1) * 32;

    for (int s0 = 0; s0 < TT; s0 += 64) {
        __syncthreads();
        const float* kr = qkv + (size_t)(b*TT + s0 + skey)*(3*CC) +   CC + h*HS + sdg;
        const float* vr = qkv + (size_t)(b*TT + s0 + skey)*(3*CC) + 2*CC + h*HS + sdg;
        #pragma unroll
        for (int j = 0; j < 8; j++) {
            uint4 kv = *(const uint4*)(kr + j*4);
            Kt[sdg + j*4 + 0][skey] = kv.x;
            Kt[sdg + j*4 + 1][skey] = kv.y;
            Kt[sdg + j*4 + 2][skey] = kv.z;
            Kt[sdg + j*4 + 3][skey] = kv.w;
            *(uint4*)&Vs[skey][sdg + j*4] = *(const uint4*)(vr + j*4);
        }
        __syncthreads();

        float sa[8][4];
        #pragma unroll
        for (int nt = 0; nt < 8; nt++)
            #pragma unroll
            for (int i = 0; i < 4; i++) sa[nt][i] = 0.f;
        #pragma unroll
        for (int ks = 0; ks < 8; ks++) {
            #pragma unroll
            for (int nt = 0; nt < 8; nt++) {
                uint32_t b0 = Kt[ks*8 + c    ][nt*8 + r];
                uint32_t b1 = Kt[ks*8 + c + 4][nt*8 + r];
                mma_tf32(sa[nt], qf[ks], b0, b1);
            }
        }

        float mx0 = -1e30f, mx1 = -1e30f;
        #pragma unroll
        for (int nt = 0; nt < 8; nt++) {
            mx0 = fmaxf(mx0, fmaxf(sa[nt][0], sa[nt][1]));
            mx1 = fmaxf(mx1, fmaxf(sa[nt][2], sa[nt][3]));
        }
        mx0 = fmaxf(mx0, __shfl_xor_sync(0xffffffff, mx0, 1));
        mx0 = fmaxf(mx0, __shfl_xor_sync(0xffffffff, mx0, 2));
        mx1 = fmaxf(mx1, __shfl_xor_sync(0xffffffff, mx1, 1));
        mx1 = fmaxf(mx1, __shfl_xor_sync(0xffffffff, mx1, 2));
        float mn0 = fmaxf(m0, mx0), mn1 = fmaxf(m1, mx1);
        float f0 = __expf(m0 - mn0), f1 = __expf(m1 - mn1);
        m0 = mn0; m1 = mn1;

        float ps0 = 0.f, ps1 = 0.f;
        const int prow = warp*16 + r;
        #pragma unroll
        for (int nt = 0; nt < 8; nt++) {
            float p0 = __expf(sa[nt][0] - mn0);
            float p1 = __expf(sa[nt][1] - mn0);
            float p2 = __expf(sa[nt][2] - mn1);
            float p3 = __expf(sa[nt][3] - mn1);
            ps0 += p0 + p1; ps1 += p2 + p3;
            uint2 w0; w0.x = f2tf32(p0); w0.y = f2tf32(p1);
            uint2 w1; w1.x = f2tf32(p2); w1.y = f2tf32(p3);
            *(uint2*)&Ps[prow    ][nt*8 + 2*c] = w0;
            *(uint2*)&Ps[prow + 8][nt*8 + 2*c] = w1;
        }
        ps0 += __shfl_xor_sync(0xffffffff, ps0, 1);
        ps0 += __shfl_xor_sync(0xffffffff, ps0, 2);
        ps1 += __shfl_xor_sync(0xffffffff, ps1, 1);
        ps1 += __shfl_xor_sync(0xffffffff, ps1, 2);
        l0 = l0 * f0 + ps0;
        l1 = l1 * f1 + ps1;

        #pragma unroll
        for (int nt = 0; nt < 8; nt++) {
            oacc[nt][0] *= f0; oacc[nt][1] *= f0;
            oacc[nt][2] *= f1; oacc[nt][3] *= f1;
        }
        __syncwarp();

        #pragma unroll
        for (int ks = 0; ks < 8; ks++) {
            uint32_t af[4];
            af[0] = Ps[prow    ][ks*8 + c    ];
            af[1] = Ps[prow + 8][ks*8 + c    ];
            af[2] = Ps[prow    ][ks*8 + c + 4];
            af[3] = Ps[prow + 8][ks*8 + c + 4];
            #pragma unroll
            for (int nt = 0; nt < 8; nt++) {
                uint32_t b0 = Vs[ks*8 + c    ][nt*8 + r];
                uint32_t b1 = Vs[ks*8 + c + 4][nt*8 + r];
                mma_tf32(oacc[nt], af, b0, b1);
            }
        }
        __syncwarp();
    }

    // write out, tf32-rounded (consumed only as O-proj GEMM A operand)
    float il0 = 1.f / l0, il1 = 1.f / l1;
    const int grow = b*TT + q0 + warp*16 + r;
    float* op0 = out + (size_t)grow * CC + h*HS;
    float* op1 = op0 + (size_t)8 * CC;
    #pragma unroll
    for (int nt = 0; nt < 8; nt++) {
        int col = nt*8 + 2*c;
        *(float2*)(op0 + col) = make_float2(rtf(oacc[nt][0]*il0), rtf(oacc[nt][1]*il0));
        *(float2*)(op1 + col) = make_float2(rtf(oacc[nt][2]*il1), rtf(oacc[nt][3]*il1));
    }
}

// ---------------- launch -----------------------------------------------
extern "C" void kernel_launch(void* const* d_in, const int* in_sizes, int n_in,
                              void* d_out, int out_size)
{
    const float* x      = (const float*)d_in[0];
    const float* Wq     = (const float*)d_in[1];
    const float* bq     = (const float*)d_in[2];
    const float* Wk     = (const float*)d_in[3];
    const float* bk     = (const float*)d_in[4];
    const float* Wv     = (const float*)d_in[5];
    const float* bv     = (const float*)d_in[6];
    const float* Wo     = (const float*)d_in[7];
    const float* bo     = (const float*)d_in[8];
    const float* W1     = (const float*)d_in[9];
    const float* b1     = (const float*)d_in[10];
    const float* W2     = (const float*)d_in[11];
    const float* b2     = (const float*)d_in[12];
    const float* gamma1 = (const float*)d_in[13];
    const float* beta1  = (const float*)d_in[14];
    const float* gamma2 = (const float*)d_in[15];
    const float* beta2  = (const float*)d_in[16];
    float* out = (float*)d_out;

    float *p_h, *p_x1, *p_attn, *p_qkv, *p_wqkv, *p_bqkv, *p_mid, *p_mean, *p_inv;
    cudaGetSymbolAddress((void**)&p_h,    g_h);
    cudaGetSymbolAddress((void**)&p_x1,   g_x1);
    cudaGetSymbolAddress((void**)&p_attn, g_attn);
    cudaGetSymbolAddress((void**)&p_qkv,  g_qkv);
    cudaGetSymbolAddress((void**)&p_wqkv, g_wqkv);
    cudaGetSymbolAddress((void**)&p_bqkv, g_bqkv);
    cudaGetSymbolAddress((void**)&p_mid,  g_mid);
    cudaGetSymbolAddress((void**)&p_mean, g_mean);
    cudaGetSymbolAddress((void**)&p_inv,  g_inv);

    dim3 lnb(32, 8);
    dim3 lng(CC/32, BB);
    const int elemBlocks = (MM*CC + 255)/256;

    // 1) LN1 (rounded output)
    ln_stats<<<lng, lnb>>>(x, p_mean, p_inv);
    ln_apply<<<elemBlocks, 256>>>(x, p_mean, p_inv, gamma1, beta1, p_h);

    // 2) pack (rounded) + fused QKV GEMM (both operands pre-rounded)
    pack_qkv<<<4096, 256>>>(Wq, Wk, Wv, bq, bk, bv, p_wqkv, p_bqkv);
    mma_gemm<false,false,true,false><<<dim3(3*CC/128, MM/128), 256>>>(
        p_h, p_wqkv, p_bqkv, nullptr, p_qkv, MM, 3*CC, CC);

    // 3) flash attention -> g_attn (rounded)
    flash_mma<<<dim3(TT/64, HH, BB), 128>>>(p_qkv, p_attn);

    // 4) output projection + residual (B = raw Wo -> BCVT)
    mma_gemm<false,true,false,true><<<dim3(CC/128, MM/128), 256>>>(
        p_attn, Wo, bo, x, p_x1, MM, CC, CC);

    // 5) LN2 (rounded output)
    ln_stats<<<lng, lnb>>>(p_x1, p_mean, p_inv);
    ln_apply<<<elemBlocks, 256>>>(p_x1, p_mean, p_inv, gamma2, beta2, p_h);

    // 6) FFN (W1, W2 raw -> BCVT; mid rounded in epilogue)
    mma_gemm<true,false,true,true><<<dim3(4*CC/128, MM/128), 256>>>(
        p_h, W1, b1, nullptr, p_mid, MM, 4*CC, CC);
    mma_gemm<false,true,false,true><<<dim3(CC/128, MM/128), 256>>>(
        p_mid, W2, b2, p_x1, out, MM, CC, 4*CC);
}

// round 6
// speedup vs baseline: 1.1993x; 1.0008x over previous
#include <cuda_runtime.h>
#include <math.h>
#include <stdint.h>

// Problem constants
#define BB 2
#define TT 2048
#define CC 1024
#define HH 16
#define HS 64
#define MM (BB*TT)          // 4096 rows
#define EPS 1e-5f

// ---------------- scratch (device globals; no runtime allocation) ----------
__device__ float g_h   [MM*CC];        // LN output, tf32-rounded
__device__ float g_x1  [MM*CC];        // after attention residual (fp32)
__device__ float g_attn[MM*CC];        // attention output, tf32-rounded
__device__ float g_qkv [MM*3*CC];      // q|k|v, tf32-rounded
__device__ float g_wqkv[CC*3*CC];      // packed qkv weight, tf32-rounded
__device__ float g_bqkv[3*CC];
__device__ float g_mid [MM*4*CC];      // FFN hidden, tf32-rounded
__device__ float g_mean[BB*CC];
__device__ float g_inv [BB*CC];

// ---------------- helpers ---------------------------------------------------
__device__ __forceinline__ uint32_t f2tf32(float f) {
    uint32_t r;
    asm("cvt.rna.tf32.f32 %0, %1;" : "=r"(r) : "f"(f));
    return r;
}
__device__ __forceinline__ float rtf(float f) { return __uint_as_float(f2tf32(f)); }

__device__ __forceinline__ void mma_tf32(float c[4], const uint32_t a[4],
                                         uint32_t b0, uint32_t b1) {
    asm("mma.sync.aligned.m16n8k8.row.col.f32.tf32.tf32.f32 "
        "{%0,%1,%2,%3},{%4,%5,%6,%7},{%8,%9},{%0,%1,%2,%3};"
        : "+f"(c[0]), "+f"(c[1]), "+f"(c[2]), "+f"(c[3])
        : "r"(a[0]), "r"(a[1]), "r"(a[2]), "r"(a[3]), "r"(b0), "r"(b1));
}

__device__ __forceinline__ void cp16(void* smem, const void* gmem) {
    uint32_t s = (uint32_t)__cvta_generic_to_shared(smem);
    asm volatile("cp.async.cg.shared.global [%0], [%1], 16;\n" :: "r"(s), "l"(gmem));
}
__device__ __forceinline__ void cp_commit() {
    asm volatile("cp.async.commit_group;\n");
}
template<int N>
__device__ __forceinline__ void cp_wait() {
    asm volatile("cp.async.wait_group %0;\n" :: "n"(N));
}

// ---------------- LayerNorm over axis=1 (sequence axis) --------------------
__global__ void ln_stats(const float* __restrict__ x,
                         float* __restrict__ mean, float* __restrict__ inv)
{
    int c = blockIdx.x * 32 + threadIdx.x;
    int b = blockIdx.y;
    float s = 0.f, ss = 0.f;
    for (int t = threadIdx.y; t < TT; t += 8) {
        float v = x[((size_t)b*TT + t)*CC + c];
        s += v; ss += v*v;
    }
    __shared__ float sh_s[8][32];
    __shared__ float sh_q[8][32];
    sh_s[threadIdx.y][threadIdx.x] = s;
    sh_q[threadIdx.y][threadIdx.x] = ss;
    __syncthreads();
    if (threadIdx.y == 0) {
        #pragma unroll
        for (int i = 1; i < 8; i++) { s += sh_s[i][threadIdx.x]; ss += sh_q[i][threadIdx.x]; }
        float mu  = s / (float)TT;
        float var = (ss - s*mu) / (float)(TT - 1);
        mean[b*CC + c] = mu;
        inv [b*CC + c] = 1.f / (sqrtf(var) + EPS);
    }
}

// writes tf32-rounded output (only consumed as a GEMM A operand)
__global__ void ln_apply(const float* __restrict__ x,
                         const float* __restrict__ mean, const float* __restrict__ inv,
                         const float* __restrict__ gamma, const float* __restrict__ beta,
                         float* __restrict__ y)
{
    int idx = blockIdx.x * blockDim.x + threadIdx.x;
    if (idx >= MM*CC) return;
    int c  = idx & (CC-1);
    int bt = idx >> 10;
    int b  = bt >> 11;
    y[idx] = rtf(gamma[c] * ((x[idx] - mean[b*CC + c]) * inv[b*CC + c]) + beta[c]);
}

// ---------------- pack Wq/Wk/Wv [H,C,HS] -> [C, 3C], tf32-rounded ----------
__global__ void pack_qkv(const float* __restrict__ Wq, const float* __restrict__ Wk,
                         const float* __restrict__ Wv,
                         const float* __restrict__ bq, const float* __restrict__ bk,
                         const float* __restrict__ bv,
                         float* __restrict__ W, float* __restrict__ bias)
{
    const int total = CC * 3 * CC;
    for (int idx = blockIdx.x * blockDim.x + threadIdx.x; idx < total;
         idx += gridDim.x * blockDim.x) {
        int k  = idx / (3*CC);
        int nn = idx % (3*CC);
        int sel = nn / CC;
        int r   = nn % CC;
        int h = r / HS, d = r % HS;
        const float* src = (sel == 0) ? Wq : (sel == 1) ? Wk : Wv;
        W[idx] = rtf(src[((size_t)h*CC + k)*HS + d]);
        if (idx < 3*CC) {
            const float* bs = (idx < CC) ? bq : (idx < 2*CC) ? bk : bv;
            bias[idx] = bs[idx % CC];
        }
    }
}

// ---------------- TF32 MMA GEMM, BK=32, 2-stage, 1 barrier/iter ------------
// 128x128 block tile, 8 warps (warp tile 32x64), m16n8k8 tf32 MMA.
// Pipeline order per iter: wait -> sync -> stage(next) -> compute.
// A operand ALWAYS pre-rounded to tf32 bits. B cvt only when BCVT.
template<bool RELU, bool RES, bool ROUND, bool BCVT>
__global__ void __launch_bounds__(256, 2) mma_gemm(
    const float* __restrict__ A, const float* __restrict__ Bm,
    const float* __restrict__ bias, const float* __restrict__ Rm,
    float* __restrict__ Cm, int M, int N, int K)
{
    __shared__ float As[2][128][36];    // [stage][m][k], stride 36: conflict-free reads
    __shared__ float Bs[2][32][136];    // [stage][k][n], stride 136: conflict-free reads

    const int tid  = threadIdx.x;
    const int lane = tid & 31;
    const int warp = tid >> 5;
    const int wm = warp & 3;
    const int wn = warp >> 2;
    const int r = lane >> 2;
    const int c = lane & 3;
    const int rowBase = blockIdx.y * 128;
    const int colBase = blockIdx.x * 128;

    float acc[2][8][4];
    #pragma unroll
    for (int mt = 0; mt < 2; mt++)
        #pragma unroll
        for (int nt = 0; nt < 8; nt++)
            #pragma unroll
            for (int i = 0; i < 4; i++) acc[mt][nt][i] = 0.f;

    const float* Ag = A + (size_t)rowBase * K;
    const float* Bg = Bm + colBase;

    auto stage = [&](int s, int k0) {
        #pragma unroll
        for (int p = 0; p < 4; p++) {
            int q = tid + p*256;
            int row = q >> 3, kc = (q & 7) * 4;
            cp16(&As[s][row][kc], Ag + (size_t)row * K + k0 + kc);
        }
        #pragma unroll
        for (int p = 0; p < 4; p++) {
            int q = tid + p*256;
            int kr = q >> 5, nc = (q & 31) * 4;
            cp16(&Bs[s][kr][nc], Bg + (size_t)(k0 + kr) * N + nc);
        }
        cp_commit();
    };

    const int nIter = K >> 5;
    stage(0, 0);

    for (int it = 0; it < nIter; it++) {
        const int s = it & 1;
        cp_wait<0>();
        __syncthreads();
        if (it + 1 < nIter) stage(s ^ 1, (it + 1) << 5);

        #pragma unroll
        for (int ks = 0; ks < 32; ks += 8) {
            uint32_t af0[4], af1[4];
            const int m0 = wm*32, m1 = wm*32 + 16;
            af0[0] = __float_as_uint(As[s][m0+r  ][ks+c  ]);
            af0[1] = __float_as_uint(As[s][m0+r+8][ks+c  ]);
            af0[2] = __float_as_uint(As[s][m0+r  ][ks+c+4]);
            af0[3] = __float_as_uint(As[s][m0+r+8][ks+c+4]);
            af1[0] = __float_as_uint(As[s][m1+r  ][ks+c  ]);
            af1[1] = __float_as_uint(As[s][m1+r+8][ks+c  ]);
            af1[2] = __float_as_uint(As[s][m1+r  ][ks+c+4]);
            af1[3] = __float_as_uint(As[s][m1+r+8][ks+c+4]);
            #pragma unroll
            for (int nt = 0; nt < 8; nt++) {
                int n = wn*64 + nt*8;
                uint32_t b0, b1;
                if (BCVT) {
                    b0 = f2tf32(Bs[s][ks+c  ][n+r]);
                    b1 = f2tf32(Bs[s][ks+c+4][n+r]);
                } else {
                    b0 = __float_as_uint(Bs[s][ks+c  ][n+r]);
                    b1 = __float_as_uint(Bs[s][ks+c+4][n+r]);
                }
                mma_tf32(acc[0][nt], af0, b0, b1);
                mma_tf32(acc[1][nt], af1, b0, b1);
            }
        }
    }

    // epilogue
    #pragma unroll
    for (int mt = 0; mt < 2; mt++) {
        #pragma unroll
        for (int nt = 0; nt < 8; nt++) {
            int row0 = rowBase + wm*32 + mt*16 + r;
            int col  = colBase + wn*64 + nt*8 + 2*c;
            float bi0 = bias[col], bi1 = bias[col+1];
            float v0 = acc[mt][nt][0] + bi0;
            float v1 = acc[mt][nt][1] + bi1;
            float v2 = acc[mt][nt][2] + bi0;
            float v3 = acc[mt][nt][3] + bi1;
            if (RELU) { v0=fmaxf(v0,0.f); v1=fmaxf(v1,0.f); v2=fmaxf(v2,0.f); v3=fmaxf(v3,0.f); }
            if (RES) {
                const float2 r0 = *(const float2*)(Rm + (size_t)row0*N + col);
                const float2 r1 = *(const float2*)(Rm + (size_t)(row0+8)*N + col);
                v0 += r0.x; v1 += r0.y; v2 += r1.x; v3 += r1.y;
            }
            if (ROUND) { v0 = rtf(v0); v1 = rtf(v1); v2 = rtf(v2); v3 = rtf(v3); }
            *(float2*)(Cm + (size_t)row0*N + col)     = make_float2(v0, v1);
            *(float2*)(Cm + (size_t)(row0+8)*N + col) = make_float2(v2, v3);
        }
    }
}

// ---------------- flash attention (tf32 MMA, non-causal, R5 structure) -----
__global__ void __launch_bounds__(128) flash_mma(const float* __restrict__ qkv,
                                                 float* __restrict__ out)
{
    __shared__ uint32_t Kt[64][72];   // [d][key]  (K transposed)
    __shared__ uint32_t Vs[64][72];   // [key][d]
    __shared__ uint32_t Ps[64][72];   // [qrow][key]

    const int tid  = threadIdx.x;
    const int lane = tid & 31;
    const int warp = tid >> 5;
    const int r = lane >> 2;
    const int c = lane & 3;
    const int b = blockIdx.z, h = blockIdx.y;
    const int q0 = blockIdx.x * 64;
    const float scale = 0.125f;       // exact power of two: preserves tf32 bits

    uint32_t qf[8][4];
    {
        const int qr0 = b*TT + q0 + warp*16 + r;
        const float* qp = qkv + (size_t)qr0 * (3*CC) + h*HS;
        const float* qp8 = qp + (size_t)8 * (3*CC);
        #pragma unroll
        for (int ks = 0; ks < 8; ks++) {
            qf[ks][0] = __float_as_uint(qp [ks*8 + c    ] * scale);
            qf[ks][1] = __float_as_uint(qp8[ks*8 + c    ] * scale);
            qf[ks][2] = __float_as_uint(qp [ks*8 + c + 4] * scale);
            qf[ks][3] = __float_as_uint(qp8[ks*8 + c + 4] * scale);
        }
    }

    float oacc[8][4];
    #pragma unroll
    for (int nt = 0; nt < 8; nt++)
        #pragma unroll
        for (int i = 0; i < 4; i++) oacc[nt][i] = 0.f;
    float m0 = -1e30f, m1 = -1e30f, l0 = 0.f, l1 = 0.f;

    const int skey = tid >> 1;
    const int sdg  = (tid & 1) * 32;

    for (int s0 = 0; s0 < TT; s0 += 64) {
        __syncthreads();
        const float* kr = qkv + (size_t)(b*TT + s0 + skey)*(3*CC) +   CC + h*HS + sdg;
        const float* vr = qkv + (size_t)(b*TT + s0 + skey)*(3*CC) + 2*CC + h*HS + sdg;
        #pragma unroll
        for (int j = 0; j < 8; j++) {
            uint4 kv = *(const uint4*)(kr + j*4);
            Kt[sdg + j*4 + 0][skey] = kv.x;
            Kt[sdg + j*4 + 1][skey] = kv.y;
            Kt[sdg + j*4 + 2][skey] = kv.z;
            Kt[sdg + j*4 + 3][skey] = kv.w;
            *(uint4*)&Vs[skey][sdg + j*4] = *(const uint4*)(vr + j*4);
        }
        __syncthreads();

        float sa[8][4];
        #pragma unroll
        for (int nt = 0; nt < 8; nt++)
            #pragma unroll
            for (int i = 0; i < 4; i++) sa[nt][i] = 0.f;
        #pragma unroll
        for (int ks = 0; ks < 8; ks++) {
            #pragma unroll
            for (int nt = 0; nt < 8; nt++) {
                uint32_t b0 = Kt[ks*8 + c    ][nt*8 + r];
                uint32_t b1 = Kt[ks*8 + c + 4][nt*8 + r];
                mma_tf32(sa[nt], qf[ks], b0, b1);
            }
        }

        float mx0 = -1e30f, mx1 = -1e30f;
        #pragma unroll
        for (int nt = 0; nt < 8; nt++) {
            mx0 = fmaxf(mx0, fmaxf(sa[nt][0], sa[nt][1]));
            mx1 = fmaxf(mx1, fmaxf(sa[nt][2], sa[nt][3]));
        }
        mx0 = fmaxf(mx0, __shfl_xor_sync(0xffffffff, mx0, 1));
        mx0 = fmaxf(mx0, __shfl_xor_sync(0xffffffff, mx0, 2));
        mx1 = fmaxf(mx1, __shfl_xor_sync(0xffffffff, mx1, 1));
        mx1 = fmaxf(mx1, __shfl_xor_sync(0xffffffff, mx1, 2));
        float mn0 = fmaxf(m0, mx0), mn1 = fmaxf(m1, mx1);
        float f0 = __expf(m0 - mn0), f1 = __expf(m1 - mn1);
        m0 = mn0; m1 = mn1;

        float ps0 = 0.f, ps1 = 0.f;
        const int prow = warp*16 + r;
        #pragma unroll
        for (int nt = 0; nt < 8; nt++) {
            float p0 = __expf(sa[nt][0] - mn0);
            float p1 = __expf(sa[nt][1] - mn0);
            float p2 = __expf(sa[nt][2] - mn1);
            float p3 = __expf(sa[nt][3] - mn1);
            ps0 += p0 + p1; ps1 += p2 + p3;
            uint2 w0; w0.x = f2tf32(p0); w0.y = f2tf32(p1);
            uint2 w1; w1.x = f2tf32(p2); w1.y = f2tf32(p3);
            *(uint2*)&Ps[prow    ][nt*8 + 2*c] = w0;
            *(uint2*)&Ps[prow + 8][nt*8 + 2*c] = w1;
        }
        ps0 += __shfl_xor_sync(0xffffffff, ps0, 1);
        ps0 += __shfl_xor_sync(0xffffffff, ps0, 2);
        ps1 += __shfl_xor_sync(0xffffffff, ps1, 1);
        ps1 += __shfl_xor_sync(0xffffffff, ps1, 2);
        l0 = l0 * f0 + ps0;
        l1 = l1 * f1 + ps1;

        #pragma unroll
        for (int nt = 0; nt < 8; nt++) {
            oacc[nt][0] *= f0; oacc[nt][1] *= f0;
            oacc[nt][2] *= f1; oacc[nt][3] *= f1;
        }
        __syncwarp();

        #pragma unroll
        for (int ks = 0; ks < 8; ks++) {
            uint32_t af[4];
            af[0] = Ps[prow    ][ks*8 + c    ];
            af[1] = Ps[prow + 8][ks*8 + c    ];
            af[2] = Ps[prow    ][ks*8 + c + 4];
            af[3] = Ps[prow + 8][ks*8 + c + 4];
            #pragma unroll
            for (int nt = 0; nt < 8; nt++) {
                uint32_t b0 = Vs[ks*8 + c    ][nt*8 + r];
                uint32_t b1 = Vs[ks*8 + c + 4][nt*8 + r];
                mma_tf32(oacc[nt], af, b0, b1);
            }
        }
        __syncwarp();
    }

    float il0 = 1.f / l0, il1 = 1.f / l1;
    const int grow = b*TT + q0 + warp*16 + r;
    float* op0 = out + (size_t)grow * CC + h*HS;
    float* op1 = op0 + (size_t)8 * CC;
    #pragma unroll
    for (int nt = 0; nt < 8; nt++) {
        int col = nt*8 + 2*c;
        *(float2*)(op0 + col) = make_float2(rtf(oacc[nt][0]*il0), rtf(oacc[nt][1]*il0));
        *(float2*)(op1 + col) = make_float2(rtf(oacc[nt][2]*il1), rtf(oacc[nt][3]*il1));
    }
}

// ---------------- launch -----------------------------------------------
extern "C" void kernel_launch(void* const* d_in, const int* in_sizes, int n_in,
                              void* d_out, int out_size)
{
    const float* x      = (const float*)d_in[0];
    const float* Wq     = (const float*)d_in[1];
    const float* bq     = (const float*)d_in[2];
    const float* Wk     = (const float*)d_in[3];
    const float* bk     = (const float*)d_in[4];
    const float* Wv     = (const float*)d_in[5];
    const float* bv     = (const float*)d_in[6];
    const float* Wo     = (const float*)d_in[7];
    const float* bo     = (const float*)d_in[8];
    const float* W1     = (const float*)d_in[9];
    const float* b1     = (const float*)d_in[10];
    const float* W2     = (const float*)d_in[11];
    const float* b2     = (const float*)d_in[12];
    const float* gamma1 = (const float*)d_in[13];
    const float* beta1  = (const float*)d_in[14];
    const float* gamma2 = (const float*)d_in[15];
    const float* beta2  = (const float*)d_in[16];
    float* out = (float*)d_out;

    float *p_h, *p_x1, *p_attn, *p_qkv, *p_wqkv, *p_bqkv, *p_mid, *p_mean, *p_inv;
    cudaGetSymbolAddress((void**)&p_h,    g_h);
    cudaGetSymbolAddress((void**)&p_x1,   g_x1);
    cudaGetSymbolAddress((void**)&p_attn, g_attn);
    cudaGetSymbolAddress((void**)&p_qkv,  g_qkv);
    cudaGetSymbolAddress((void**)&p_wqkv, g_wqkv);
    cudaGetSymbolAddress((void**)&p_bqkv, g_bqkv);
    cudaGetSymbolAddress((void**)&p_mid,  g_mid);
    cudaGetSymbolAddress((void**)&p_mean, g_mean);
    cudaGetSymbolAddress((void**)&p_inv,  g_inv);

    dim3 lnb(32, 8);
    dim3 lng(CC/32, BB);
    const int elemBlocks = (MM*CC + 255)/256;

    // 1) LN1 (rounded output)
    ln_stats<<<lng, lnb>>>(x, p_mean, p_inv);
    ln_apply<<<elemBlocks, 256>>>(x, p_mean, p_inv, gamma1, beta1, p_h);

    // 2) pack (rounded) + fused QKV GEMM (both operands pre-rounded)
    pack_qkv<<<4096, 256>>>(Wq, Wk, Wv, bq, bk, bv, p_wqkv, p_bqkv);
    mma_gemm<false,false,true,false><<<dim3(3*CC/128, MM/128), 256>>>(
        p_h, p_wqkv, p_bqkv, nullptr, p_qkv, MM, 3*CC, CC);

    // 3) flash attention -> g_attn (rounded)
    flash_mma<<<dim3(TT/64, HH, BB), 128>>>(p_qkv, p_attn);

    // 4) output projection + residual (B = raw Wo -> BCVT)
    mma_gemm<false,true,false,true><<<dim3(CC/128, MM/128), 256>>>(
        p_attn, Wo, bo, x, p_x1, MM, CC, CC);

    // 5) LN2 (rounded output)
    ln_stats<<<lng, lnb>>>(p_x1, p_mean, p_inv);
    ln_apply<<<elemBlocks, 256>>>(p_x1, p_mean, p_inv, gamma2, beta2, p_h);

    // 6) FFN (W1, W2 raw -> BCVT; mid rounded in epilogue)
    mma_gemm<true,false,true,true><<<dim3(4*CC/128, MM/128), 256>>>(
        p_h, W1, b1, nullptr, p_mid, MM, 4*CC, CC);
    mma_gemm<false,true,false,true><<<dim3(CC/128, MM/128), 256>>>(
        p_mid, W2, b2, p_x1, out, MM, CC, 4*CC);
}

// round 8
// speedup vs baseline: 2.3652x; 1.9722x over previous
#include <cuda_runtime.h>
#include <cuda_fp16.h>
#include <math.h>
#include <stdint.h>

// Problem constants
#define BB 2
#define TT 2048
#define CC 1024
#define HH 16
#define HS 64
#define MM (BB*TT)          // 4096 rows
#define EPS 1e-5f

// ---------------- scratch (device globals; no runtime allocation) ----------
__device__ __align__(16) __half g_h   [MM*CC];      // LN output, fp16
__device__ float                g_x1  [MM*CC];      // after attention residual (fp32)
__device__ __align__(16) __half g_attn[MM*CC];      // attention output, fp16
__device__ __align__(16) __half g_qkv [MM*3*CC];    // q|k|v, fp16
__device__ __align__(16) __half g_wqkv[3*CC*CC];    // packed qkv weight [3C][C] K-major fp16
__device__ float                g_bqkv[3*CC];
__device__ __align__(16) __half g_mid [MM*4*CC];    // FFN hidden, fp16
__device__ __align__(16) __half g_wot [CC*CC];      // Wo^T  [C][C]   fp16
__device__ __align__(16) __half g_w1t [4*CC*CC];    // W1^T  [4C][C]  fp16
__device__ __align__(16) __half g_w2t [CC*4*CC];    // W2^T  [C][4C]  fp16
__device__ float                g_mean[BB*CC];
__device__ float                g_inv [BB*CC];

// ---------------- helpers ---------------------------------------------------
__device__ __forceinline__ void mma_f16(float c[4], const uint32_t a[4],
                                        uint32_t b0, uint32_t b1) {
    asm("mma.sync.aligned.m16n8k16.row.col.f32.f16.f16.f32 "
        "{%0,%1,%2,%3},{%4,%5,%6,%7},{%8,%9},{%0,%1,%2,%3};"
        : "+f"(c[0]), "+f"(c[1]), "+f"(c[2]), "+f"(c[3])
        : "r"(a[0]), "r"(a[1]), "r"(a[2]), "r"(a[3]), "r"(b0), "r"(b1));
}

__device__ __forceinline__ void cp16(void* smem, const void* gmem) {
    uint32_t s = (uint32_t)__cvta_generic_to_shared(smem);
    asm volatile("cp.async.cg.shared.global [%0], [%1], 16;\n" :: "r"(s), "l"(gmem));
}
__device__ __forceinline__ void cp_commit() {
    asm volatile("cp.async.commit_group;\n");
}
template<int N>
__device__ __forceinline__ void cp_wait() {
    asm volatile("cp.async.wait_group %0;\n" :: "n"(N));
}

// ---------------- LayerNorm over axis=1 (sequence axis) --------------------
__global__ void ln_stats(const float* __restrict__ x,
                         float* __restrict__ mean, float* __restrict__ inv)
{
    int c = blockIdx.x * 32 + threadIdx.x;
    int b = blockIdx.y;
    float s = 0.f, ss = 0.f;
    for (int t = threadIdx.y; t < TT; t += 8) {
        float v = x[((size_t)b*TT + t)*CC + c];
        s += v; ss += v*v;
    }
    __shared__ float sh_s[8][32];
    __shared__ float sh_q[8][32];
    sh_s[threadIdx.y][threadIdx.x] = s;
    sh_q[threadIdx.y][threadIdx.x] = ss;
    __syncthreads();
    if (threadIdx.y == 0) {
        #pragma unroll
        for (int i = 1; i < 8; i++) { s += sh_s[i][threadIdx.x]; ss += sh_q[i][threadIdx.x]; }
        float mu  = s / (float)TT;
        float var = (ss - s*mu) / (float)(TT - 1);
        mean[b*CC + c] = mu;
        inv [b*CC + c] = 1.f / (sqrtf(var) + EPS);
    }
}

// writes fp16 output (only consumed as a GEMM A operand)
__global__ void ln_apply(const float* __restrict__ x,
                         const float* __restrict__ mean, const float* __restrict__ inv,
                         const float* __restrict__ gamma, const float* __restrict__ beta,
                         __half* __restrict__ y)
{
    int idx = blockIdx.x * blockDim.x + threadIdx.x;
    if (idx >= MM*CC) return;
    int c  = idx & (CC-1);
    int bt = idx >> 10;
    int b  = bt >> 11;
    y[idx] = __float2half(gamma[c] * ((x[idx] - mean[b*CC + c]) * inv[b*CC + c]) + beta[c]);
}

// ---------------- weight transposes (to K-major [N][K], fp16) --------------
__global__ void transpose_h(const float* __restrict__ src, __half* __restrict__ dst,
                            int K, int N)
{
    __shared__ float t[32][33];
    int kb = blockIdx.x * 32, nb = blockIdx.y * 32;
    #pragma unroll
    for (int i = threadIdx.y; i < 32; i += 8)
        t[i][threadIdx.x] = src[(size_t)(kb + i)*N + nb + threadIdx.x];
    __syncthreads();
    #pragma unroll
    for (int i = threadIdx.y; i < 32; i += 8)
        dst[(size_t)(nb + i)*K + kb + threadIdx.x] = __float2half(t[threadIdx.x][i]);
}

// pack Wq/Wk/Wv [H,C,HS] -> [3C][C] K-major fp16
__global__ void pack_qkv_t(const float* __restrict__ Wq, const float* __restrict__ Wk,
                           const float* __restrict__ Wv, __half* __restrict__ W)
{
    __shared__ float t[32][33];
    int z = blockIdx.y;
    int dt = z & 1;  z >>= 1;
    int h  = z & 15; z >>= 4;
    int sel = z;
    const float* src = (sel == 0) ? Wq : (sel == 1) ? Wk : Wv;
    int kb = blockIdx.x * 32, db = dt * 32;
    #pragma unroll
    for (int i = threadIdx.y; i < 32; i += 8)
        t[i][threadIdx.x] = src[((size_t)h*CC + kb + i)*HS + db + threadIdx.x];
    __syncthreads();
    #pragma unroll
    for (int i = threadIdx.y; i < 32; i += 8) {
        int n = sel*CC + h*HS + db + i;
        W[(size_t)n*CC + kb + threadIdx.x] = __float2half(t[threadIdx.x][i]);
    }
}

__global__ void pack_bias(const float* __restrict__ bq, const float* __restrict__ bk,
                          const float* __restrict__ bv, float* __restrict__ bias)
{
    int i = blockIdx.x * 1024 + threadIdx.x;
    const float* s = (i < CC) ? bq : (i < 2*CC) ? bk : bv;
    bias[i] = s[i & (CC-1)];
}

// ---------------- FP16 MMA GEMM, BK=64, 2-stage, 1 barrier/iter ------------
// CTA tile 128x128, 8 warps (warp tile 32x64), m16n8k16 fp16, fp32 accum.
// A [M][K] row-major fp16. Bt [N][K] row-major fp16 (= K-major B).
template<bool RELU, bool RES, bool OUTH>
__global__ void __launch_bounds__(256, 2) h_gemm(
    const __half* __restrict__ A, const __half* __restrict__ Bt,
    const float* __restrict__ bias, const float* __restrict__ Rm,
    void* __restrict__ Cout, int M, int N, int K)
{
    __shared__ __half As[2][128][72];   // [stage][m][k], stride 72 halves: conflict-free
    __shared__ __half Bs[2][128][72];   // [stage][n][k]

    const int tid  = threadIdx.x;
    const int lane = tid & 31;
    const int warp = tid >> 5;
    const int wm = warp & 3;
    const int wn = warp >> 2;
    const int r = lane >> 2;
    const int c = lane & 3;
    const int rowBase = blockIdx.y * 128;
    const int colBase = blockIdx.x * 128;

    float acc[2][8][4];
    #pragma unroll
    for (int mt = 0; mt < 2; mt++)
        #pragma unroll
        for (int nt = 0; nt < 8; nt++)
            #pragma unroll
            for (int i = 0; i < 4; i++) acc[mt][nt][i] = 0.f;

    const __half* Ag = A  + (size_t)rowBase * K;
    const __half* Bg = Bt + (size_t)colBase * K;

    auto stage = [&](int s, int k0) {
        #pragma unroll
        for (int p = 0; p < 4; p++) {
            int q = tid + p*256;
            int row = q >> 3, kc = (q & 7) * 8;
            cp16(&As[s][row][kc], Ag + (size_t)row * K + k0 + kc);
        }
        #pragma unroll
        for (int p = 0; p < 4; p++) {
            int q = tid + p*256;
            int row = q >> 3, kc = (q & 7) * 8;
            cp16(&Bs[s][row][kc], Bg + (size_t)row * K + k0 + kc);
        }
        cp_commit();
    };

    const int nIter = K >> 6;
    stage(0, 0);

    for (int it = 0; it < nIter; it++) {
        const int s = it & 1;
        cp_wait<0>();
        __syncthreads();
        if (it + 1 < nIter) stage(s ^ 1, (it + 1) << 6);

        #pragma unroll
        for (int ks = 0; ks < 4; ks++) {
            const int k2 = ks*16 + 2*c;
            uint32_t af0[4], af1[4];
            const int m0 = wm*32, m1 = wm*32 + 16;
            af0[0] = *(const uint32_t*)&As[s][m0+r  ][k2  ];
            af0[1] = *(const uint32_t*)&As[s][m0+r+8][k2  ];
            af0[2] = *(const uint32_t*)&As[s][m0+r  ][k2+8];
            af0[3] = *(const uint32_t*)&As[s][m0+r+8][k2+8];
            af1[0] = *(const uint32_t*)&As[s][m1+r  ][k2  ];
            af1[1] = *(const uint32_t*)&As[s][m1+r+8][k2  ];
            af1[2] = *(const uint32_t*)&As[s][m1+r  ][k2+8];
            af1[3] = *(const uint32_t*)&As[s][m1+r+8][k2+8];
            #pragma unroll
            for (int nt = 0; nt < 8; nt++) {
                int n = wn*64 + nt*8 + r;
                uint32_t b0 = *(const uint32_t*)&Bs[s][n][k2  ];
                uint32_t b1 = *(const uint32_t*)&Bs[s][n][k2+8];
                mma_f16(acc[0][nt], af0, b0, b1);
                mma_f16(acc[1][nt], af1, b0, b1);
            }
        }
    }

    // epilogue
    #pragma unroll
    for (int mt = 0; mt < 2; mt++) {
        #pragma unroll
        for (int nt = 0; nt < 8; nt++) {
            int row0 = rowBase + wm*32 + mt*16 + r;
            int col  = colBase + wn*64 + nt*8 + 2*c;
            float bi0 = bias[col], bi1 = bias[col+1];
            float v0 = acc[mt][nt][0] + bi0;
            float v1 = acc[mt][nt][1] + bi1;
            float v2 = acc[mt][nt][2] + bi0;
            float v3 = acc[mt][nt][3] + bi1;
            if (RELU) { v0=fmaxf(v0,0.f); v1=fmaxf(v1,0.f); v2=fmaxf(v2,0.f); v3=fmaxf(v3,0.f); }
            if (RES) {
                const float2 r0 = *(const float2*)(Rm + (size_t)row0*N + col);
                const float2 r1 = *(const float2*)(Rm + (size_t)(row0+8)*N + col);
                v0 += r0.x; v1 += r0.y; v2 += r1.x; v3 += r1.y;
            }
            if (OUTH) {
                __half* C = (__half*)Cout;
                *(__half2*)(C + (size_t)row0*N + col)     = __floats2half2_rn(v0, v1);
                *(__half2*)(C + (size_t)(row0+8)*N + col) = __floats2half2_rn(v2, v3);
            } else {
                float* C = (float*)Cout;
                *(float2*)(C + (size_t)row0*N + col)     = make_float2(v0, v1);
                *(float2*)(C + (size_t)(row0+8)*N + col) = make_float2(v2, v3);
            }
        }
    }
}

// ---------------- flash attention (fp16 MMA, non-causal) -------------------
// grid (T/64, H, B); 128 threads = 4 warps; each warp owns 16 query rows.
__global__ void __launch_bounds__(128) flash_h(const __half* __restrict__ qkv,
                                               __half* __restrict__ out)
{
    __shared__ __half Ks[64][72];   // [key][d]   (natural — fp16 B wants n-major)
    __shared__ __half Vt[64][72];   // [d][key]   (transposed)
    __shared__ __half Ps[64][72];   // [qrow][key]

    const int tid  = threadIdx.x;
    const int lane = tid & 31;
    const int warp = tid >> 5;
    const int r = lane >> 2;
    const int c = lane & 3;
    const int b = blockIdx.z, h = blockIdx.y;
    const int q0 = blockIdx.x * 64;

    // Q fragments (fp16 in gmem), scaled by 0.125 (exact in fp16)
    uint32_t qf[4][4];
    {
        const __half2 sc = __floats2half2_rn(0.125f, 0.125f);
        const __half* qp  = qkv + (size_t)(b*TT + q0 + warp*16 + r) * (3*CC) + h*HS;
        const __half* qp8 = qp + (size_t)8 * (3*CC);
        #pragma unroll
        for (int ks = 0; ks < 4; ks++) {
            const int k2 = ks*16 + 2*c;
            __half2 a0 = __hmul2(*(const __half2*)(qp  + k2    ), sc);
            __half2 a1 = __hmul2(*(const __half2*)(qp8 + k2    ), sc);
            __half2 a2 = __hmul2(*(const __half2*)(qp  + k2 + 8), sc);
            __half2 a3 = __hmul2(*(const __half2*)(qp8 + k2 + 8), sc);
            qf[ks][0] = *(uint32_t*)&a0;
            qf[ks][1] = *(uint32_t*)&a1;
            qf[ks][2] = *(uint32_t*)&a2;
            qf[ks][3] = *(uint32_t*)&a3;
        }
    }

    float oacc[8][4];
    #pragma unroll
    for (int nt = 0; nt < 8; nt++)
        #pragma unroll
        for (int i = 0; i < 4; i++) oacc[nt][i] = 0.f;
    float m0 = -1e30f, m1 = -1e30f, l0 = 0.f, l1 = 0.f;

    const int skey = tid >> 1;          // 0..63
    const int part = tid & 1;           // half-row: d in [part*32, part*32+32)

    for (int s0 = 0; s0 < TT; s0 += 64) {
        __syncthreads();
        const __half* kr = qkv + (size_t)(b*TT + s0 + skey)*(3*CC) +   CC + h*HS + part*32;
        const __half* vr = qkv + (size_t)(b*TT + s0 + skey)*(3*CC) + 2*CC + h*HS + part*32;
        // K: straight copy (natural layout)
        {
            const uint4* src = (const uint4*)kr;
            uint4* dst = (uint4*)&Ks[skey][part*32];
            #pragma unroll
            for (int j = 0; j < 4; j++) dst[j] = src[j];
        }
        // V: transpose into Vt[d][key]
        {
            const uint4* src = (const uint4*)vr;
            #pragma unroll
            for (int jj = 0; jj < 4; jj++) {
                union { uint4 u; __half hh[8]; } uv;
                uv.u = src[jj];
                #pragma unroll
                for (int k = 0; k < 8; k++)
                    Vt[part*32 + jj*8 + k][skey] = uv.hh[k];
            }
        }
        __syncthreads();

        // S = Q K^T  (warp: 16 x 64)
        float sa[8][4];
        #pragma unroll
        for (int nt = 0; nt < 8; nt++)
            #pragma unroll
            for (int i = 0; i < 4; i++) sa[nt][i] = 0.f;
        #pragma unroll
        for (int ks = 0; ks < 4; ks++) {
            const int k2 = ks*16 + 2*c;
            #pragma unroll
            for (int nt = 0; nt < 8; nt++) {
                int n = nt*8 + r;
                uint32_t b0 = *(const uint32_t*)&Ks[n][k2  ];
                uint32_t b1 = *(const uint32_t*)&Ks[n][k2+8];
                mma_f16(sa[nt], qf[ks], b0, b1);
            }
        }

        // online softmax
        float mx0 = -1e30f, mx1 = -1e30f;
        #pragma unroll
        for (int nt = 0; nt < 8; nt++) {
            mx0 = fmaxf(mx0, fmaxf(sa[nt][0], sa[nt][1]));
            mx1 = fmaxf(mx1, fmaxf(sa[nt][2], sa[nt][3]));
        }
        mx0 = fmaxf(mx0, __shfl_xor_sync(0xffffffff, mx0, 1));
        mx0 = fmaxf(mx0, __shfl_xor_sync(0xffffffff, mx0, 2));
        mx1 = fmaxf(mx1, __shfl_xor_sync(0xffffffff, mx1, 1));
        mx1 = fmaxf(mx1, __shfl_xor_sync(0xffffffff, mx1, 2));
        float mn0 = fmaxf(m0, mx0), mn1 = fmaxf(m1, mx1);
        float f0 = __expf(m0 - mn0), f1 = __expf(m1 - mn1);
        m0 = mn0; m1 = mn1;

        float ps0 = 0.f, ps1 = 0.f;
        const int prow = warp*16 + r;
        #pragma unroll
        for (int nt = 0; nt < 8; nt++) {
            float p0 = __expf(sa[nt][0] - mn0);
            float p1 = __expf(sa[nt][1] - mn0);
            float p2 = __expf(sa[nt][2] - mn1);
            float p3 = __expf(sa[nt][3] - mn1);
            ps0 += p0 + p1; ps1 += p2 + p3;
            *(__half2*)&Ps[prow    ][nt*8 + 2*c] = __floats2half2_rn(p0, p1);
            *(__half2*)&Ps[prow + 8][nt*8 + 2*c] = __floats2half2_rn(p2, p3);
        }
        ps0 += __shfl_xor_sync(0xffffffff, ps0, 1);
        ps0 += __shfl_xor_sync(0xffffffff, ps0, 2);
        ps1 += __shfl_xor_sync(0xffffffff, ps1, 1);
        ps1 += __shfl_xor_sync(0xffffffff, ps1, 2);
        l0 = l0 * f0 + ps0;
        l1 = l1 * f1 + ps1;

        #pragma unroll
        for (int nt = 0; nt < 8; nt++) {
            oacc[nt][0] *= f0; oacc[nt][1] *= f0;
            oacc[nt][2] *= f1; oacc[nt][3] *= f1;
        }
        __syncwarp();

        // O += P V  (A = P from smem, B = V^T n-major)
        #pragma unroll
        for (int ks = 0; ks < 4; ks++) {
            const int k2 = ks*16 + 2*c;
            uint32_t af[4];
            af[0] = *(const uint32_t*)&Ps[prow    ][k2  ];
            af[1] = *(const uint32_t*)&Ps[prow + 8][k2  ];
            af[2] = *(const uint32_t*)&Ps[prow    ][k2+8];
            af[3] = *(const uint32_t*)&Ps[prow + 8][k2+8];
            #pragma unroll
            for (int nt = 0; nt < 8; nt++) {
                int n = nt*8 + r;
                uint32_t b0 = *(const uint32_t*)&Vt[n][k2  ];
                uint32_t b1 = *(const uint32_t*)&Vt[n][k2+8];
                mma_f16(oacc[nt], af, b0, b1);
            }
        }
        __syncwarp();
    }

    // write out fp16 (head-concat layout; consumed as O-proj GEMM A operand)
    float il0 = 1.f / l0, il1 = 1.f / l1;
    const int grow = b*TT + q0 + warp*16 + r;
    __half* op0 = out + (size_t)grow * CC + h*HS;
    __half* op1 = op0 + (size_t)8 * CC;
    #pragma unroll
    for (int nt = 0; nt < 8; nt++) {
        int col = nt*8 + 2*c;
        *(__half2*)(op0 + col) = __floats2half2_rn(oacc[nt][0]*il0, oacc[nt][1]*il0);
        *(__half2*)(op1 + col) = __floats2half2_rn(oacc[nt][2]*il1, oacc[nt][3]*il1);
    }
}

// ---------------- launch -----------------------------------------------
extern "C" void kernel_launch(void* const* d_in, const int* in_sizes, int n_in,
                              void* d_out, int out_size)
{
    const float* x      = (const float*)d_in[0];
    const float* Wq     = (const float*)d_in[1];
    const float* bq     = (const float*)d_in[2];
    const float* Wk     = (const float*)d_in[3];
    const float* bk     = (const float*)d_in[4];
    const float* Wv     = (const float*)d_in[5];
    const float* bv     = (const float*)d_in[6];
    const float* Wo     = (const float*)d_in[7];
    const float* bo     = (const float*)d_in[8];
    const float* W1     = (const float*)d_in[9];
    const float* b1     = (const float*)d_in[10];
    const float* W2     = (const float*)d_in[11];
    const float* b2     = (const float*)d_in[12];
    const float* gamma1 = (const float*)d_in[13];
    const float* beta1  = (const float*)d_in[14];
    const float* gamma2 = (const float*)d_in[15];
    const float* beta2  = (const float*)d_in[16];
    float* out = (float*)d_out;

    __half *p_h, *p_attn, *p_qkv, *p_wqkv, *p_mid, *p_wot, *p_w1t, *p_w2t;
    float *p_x1, *p_bqkv, *p_mean, *p_inv;
    cudaGetSymbolAddress((void**)&p_h,    g_h);
    cudaGetSymbolAddress((void**)&p_x1,   g_x1);
    cudaGetSymbolAddress((void**)&p_attn, g_attn);
    cudaGetSymbolAddress((void**)&p_qkv,  g_qkv);
    cudaGetSymbolAddress((void**)&p_wqkv, g_wqkv);
    cudaGetSymbolAddress((void**)&p_bqkv, g_bqkv);
    cudaGetSymbolAddress((void**)&p_mid,  g_mid);
    cudaGetSymbolAddress((void**)&p_mean, g_mean);
    cudaGetSymbolAddress((void**)&p_inv,  g_inv);
    cudaGetSymbolAddress((void**)&p_wot,  g_wot);
    cudaGetSymbolAddress((void**)&p_w1t,  g_w1t);
    cudaGetSymbolAddress((void**)&p_w2t,  g_w2t);

    dim3 lnb(32, 8);
    dim3 lng(CC/32, BB);
    const int elemBlocks = (MM*CC + 255)/256;
    dim3 tb(32, 8);

    // 0) weight prep: transpose to K-major [N][K] + fp16 cvt
    transpose_h<<<dim3(32, 32),  tb>>>(Wo, p_wot, CC,   CC);
    transpose_h<<<dim3(32, 128), tb>>>(W1, p_w1t, CC,   4*CC);
    transpose_h<<<dim3(128, 32), tb>>>(W2, p_w2t, 4*CC, CC);
    pack_qkv_t<<<dim3(32, 96), tb>>>(Wq, Wk, Wv, p_wqkv);
    pack_bias<<<3, 1024>>>(bq, bk, bv, p_bqkv);

    // 1) LN1 (fp16 output)
    ln_stats<<<lng, lnb>>>(x, p_mean, p_inv);
    ln_apply<<<elemBlocks, 256>>>(x, p_mean, p_inv, gamma1, beta1, p_h);

    // 2) fused QKV GEMM -> g_qkv [4096, 3072] fp16
    h_gemm<false,false,true><<<dim3(3*CC/128, MM/128), 256>>>(
        p_h, p_wqkv, p_bqkv, nullptr, p_qkv, MM, 3*CC, CC);

    // 3) flash attention -> g_attn fp16
    flash_h<<<dim3(TT/64, HH, BB), 128>>>(p_qkv, p_attn);

    // 4) output projection + residual -> g_x1 (fp32)
    h_gemm<false,true,false><<<dim3(CC/128, MM/128), 256>>>(
        p_attn, p_wot, bo, x, p_x1, MM, CC, CC);

    // 5) LN2 (fp16 output)
    ln_stats<<<lng, lnb>>>(p_x1, p_mean, p_inv);
    ln_apply<<<elemBlocks, 256>>>(p_x1, p_mean, p_inv, gamma2, beta2, p_h);

    // 6) FFN
    h_gemm<true,false,true><<<dim3(4*CC/128, MM/128), 256>>>(
        p_h, p_w1t, b1, nullptr, p_mid, MM, 4*CC, CC);
    h_gemm<false,true,false><<<dim3(CC/128, MM/128), 256>>>(
        p_mid, p_w2t, b2, p_x1, out, MM, CC, 4*CC);
}

// round 9
// speedup vs baseline: 2.7313x; 1.1548x over previous
#include <cuda_runtime.h>
#include <cuda_fp16.h>
#include <math.h>
#include <stdint.h>

// Problem constants
#define BB 2
#define TT 2048
#define CC 1024
#define HH 16
#define HS 64
#define MM (BB*TT)          // 4096 rows
#define EPS 1e-5f

// ---------------- scratch (device globals; no runtime allocation) ----------
__device__ __align__(16) __half g_h   [MM*CC];      // LN output, fp16
__device__ float                g_x1  [MM*CC];      // after attention residual (fp32)
__device__ __align__(16) __half g_attn[MM*CC];      // attention output, fp16
__device__ __align__(16) __half g_qkv [MM*3*CC];    // q|k|v, fp16
__device__ __align__(16) __half g_wqkv[3*CC*CC];    // packed qkv weight [3C][C] K-major fp16
__device__ float                g_bqkv[3*CC];
__device__ __align__(16) __half g_mid [MM*4*CC];    // FFN hidden, fp16
__device__ __align__(16) __half g_wot [CC*CC];      // Wo^T  [C][C]   fp16
__device__ __align__(16) __half g_w1t [4*CC*CC];    // W1^T  [4C][C]  fp16
__device__ __align__(16) __half g_w2t [CC*4*CC];    // W2^T  [C][4C]  fp16
__device__ float                g_mean[BB*CC];
__device__ float                g_inv [BB*CC];

// ---------------- helpers ---------------------------------------------------
__device__ __forceinline__ void mma_f16(float c[4], const uint32_t a[4],
                                        uint32_t b0, uint32_t b1) {
    asm("mma.sync.aligned.m16n8k16.row.col.f32.f16.f16.f32 "
        "{%0,%1,%2,%3},{%4,%5,%6,%7},{%8,%9},{%0,%1,%2,%3};"
        : "+f"(c[0]), "+f"(c[1]), "+f"(c[2]), "+f"(c[3])
        : "r"(a[0]), "r"(a[1]), "r"(a[2]), "r"(a[3]), "r"(b0), "r"(b1));
}

__device__ __forceinline__ void ldm_x4(uint32_t& r0, uint32_t& r1,
                                       uint32_t& r2, uint32_t& r3, uint32_t addr) {
    asm volatile("ldmatrix.sync.aligned.m8n8.x4.shared.b16 {%0,%1,%2,%3}, [%4];"
        : "=r"(r0), "=r"(r1), "=r"(r2), "=r"(r3) : "r"(addr));
}
__device__ __forceinline__ void ldm_x4_t(uint32_t& r0, uint32_t& r1,
                                         uint32_t& r2, uint32_t& r3, uint32_t addr) {
    asm volatile("ldmatrix.sync.aligned.m8n8.x4.trans.shared.b16 {%0,%1,%2,%3}, [%4];"
        : "=r"(r0), "=r"(r1), "=r"(r2), "=r"(r3) : "r"(addr));
}

__device__ __forceinline__ void cp16(void* smem, const void* gmem) {
    uint32_t s = (uint32_t)__cvta_generic_to_shared(smem);
    asm volatile("cp.async.cg.shared.global [%0], [%1], 16;\n" :: "r"(s), "l"(gmem));
}
__device__ __forceinline__ void cp_commit() {
    asm volatile("cp.async.commit_group;\n");
}
template<int N>
__device__ __forceinline__ void cp_wait() {
    asm volatile("cp.async.wait_group %0;\n" :: "n"(N));
}
__device__ __forceinline__ uint32_t s2u(const void* p) {
    return (uint32_t)__cvta_generic_to_shared(p);
}

// ---------------- LayerNorm over axis=1 (sequence axis) --------------------
__global__ void ln_stats(const float* __restrict__ x,
                         float* __restrict__ mean, float* __restrict__ inv)
{
    int c = blockIdx.x * 32 + threadIdx.x;
    int b = blockIdx.y;
    float s = 0.f, ss = 0.f;
    for (int t = threadIdx.y; t < TT; t += 8) {
        float v = x[((size_t)b*TT + t)*CC + c];
        s += v; ss += v*v;
    }
    __shared__ float sh_s[8][32];
    __shared__ float sh_q[8][32];
    sh_s[threadIdx.y][threadIdx.x] = s;
    sh_q[threadIdx.y][threadIdx.x] = ss;
    __syncthreads();
    if (threadIdx.y == 0) {
        #pragma unroll
        for (int i = 1; i < 8; i++) { s += sh_s[i][threadIdx.x]; ss += sh_q[i][threadIdx.x]; }
        float mu  = s / (float)TT;
        float var = (ss - s*mu) / (float)(TT - 1);
        mean[b*CC + c] = mu;
        inv [b*CC + c] = 1.f / (sqrtf(var) + EPS);
    }
}

__global__ void ln_apply(const float* __restrict__ x,
                         const float* __restrict__ mean, const float* __restrict__ inv,
                         const float* __restrict__ gamma, const float* __restrict__ beta,
                         __half* __restrict__ y)
{
    int idx = blockIdx.x * blockDim.x + threadIdx.x;
    if (idx >= MM*CC) return;
    int c  = idx & (CC-1);
    int bt = idx >> 10;
    int b  = bt >> 11;
    y[idx] = __float2half(gamma[c] * ((x[idx] - mean[b*CC + c]) * inv[b*CC + c]) + beta[c]);
}

// ---------------- weight transposes (to K-major [N][K], fp16) --------------
__global__ void transpose_h(const float* __restrict__ src, __half* __restrict__ dst,
                            int K, int N)
{
    __shared__ float t[32][33];
    int kb = blockIdx.x * 32, nb = blockIdx.y * 32;
    #pragma unroll
    for (int i = threadIdx.y; i < 32; i += 8)
        t[i][threadIdx.x] = src[(size_t)(kb + i)*N + nb + threadIdx.x];
    __syncthreads();
    #pragma unroll
    for (int i = threadIdx.y; i < 32; i += 8)
        dst[(size_t)(nb + i)*K + kb + threadIdx.x] = __float2half(t[threadIdx.x][i]);
}

__global__ void pack_qkv_t(const float* __restrict__ Wq, const float* __restrict__ Wk,
                           const float* __restrict__ Wv, __half* __restrict__ W)
{
    __shared__ float t[32][33];
    int z = blockIdx.y;
    int dt = z & 1;  z >>= 1;
    int h  = z & 15; z >>= 4;
    int sel = z;
    const float* src = (sel == 0) ? Wq : (sel == 1) ? Wk : Wv;
    int kb = blockIdx.x * 32, db = dt * 32;
    #pragma unroll
    for (int i = threadIdx.y; i < 32; i += 8)
        t[i][threadIdx.x] = src[((size_t)h*CC + kb + i)*HS + db + threadIdx.x];
    __syncthreads();
    #pragma unroll
    for (int i = threadIdx.y; i < 32; i += 8) {
        int n = sel*CC + h*HS + db + i;
        W[(size_t)n*CC + kb + threadIdx.x] = __float2half(t[threadIdx.x][i]);
    }
}

__global__ void pack_bias(const float* __restrict__ bq, const float* __restrict__ bk,
                          const float* __restrict__ bv, float* __restrict__ bias)
{
    int i = blockIdx.x * 1024 + threadIdx.x;
    const float* s = (i < CC) ? bq : (i < 2*CC) ? bk : bv;
    bias[i] = s[i & (CC-1)];
}

// ---------------- FP16 MMA GEMM, BK=64, 2-stage, ldmatrix fragments --------
// CTA tile 128x128, 8 warps (warp tile 32x64), m16n8k16, fp32 accum.
template<bool RELU, bool RES, bool OUTH>
__global__ void __launch_bounds__(256, 2) h_gemm(
    const __half* __restrict__ A, const __half* __restrict__ Bt,
    const float* __restrict__ bias, const float* __restrict__ Rm,
    void* __restrict__ Cout, int M, int N, int K)
{
    __shared__ __half As[2][128][72];
    __shared__ __half Bs[2][128][72];

    const int tid  = threadIdx.x;
    const int lane = tid & 31;
    const int warp = tid >> 5;
    const int wm = warp & 3;
    const int wn = warp >> 2;
    const int r = lane >> 2;
    const int c = lane & 3;
    const int j  = lane >> 3;         // ldmatrix matrix id
    const int rr = lane & 7;          // ldmatrix row-in-matrix
    const int rowBase = blockIdx.y * 128;
    const int colBase = blockIdx.x * 128;

    float acc[2][8][4];
    #pragma unroll
    for (int mt = 0; mt < 2; mt++)
        #pragma unroll
        for (int nt = 0; nt < 8; nt++)
            #pragma unroll
            for (int i = 0; i < 4; i++) acc[mt][nt][i] = 0.f;

    const __half* Ag = A  + (size_t)rowBase * K;
    const __half* Bg = Bt + (size_t)colBase * K;

    auto stage = [&](int s, int k0) {
        #pragma unroll
        for (int p = 0; p < 4; p++) {
            int q = tid + p*256;
            int row = q >> 3, kc = (q & 7) * 8;
            cp16(&As[s][row][kc], Ag + (size_t)row * K + k0 + kc);
        }
        #pragma unroll
        for (int p = 0; p < 4; p++) {
            int q = tid + p*256;
            int row = q >> 3, kc = (q & 7) * 8;
            cp16(&Bs[s][row][kc], Bg + (size_t)row * K + k0 + kc);
        }
        cp_commit();
    };

    // per-lane ldmatrix address components
    const int aRow = wm*32 + (j & 1)*8 + rr;   // + mt*16
    const int aCol = (j >> 1) * 8;             // + ks*16
    const int bRow = wn*64 + (j >> 1)*8 + rr;  // + tp*16
    const int bCol = (j & 1) * 8;              // + ks*16

    const int nIter = K >> 6;
    stage(0, 0);

    for (int it = 0; it < nIter; it++) {
        const int s = it & 1;
        cp_wait<0>();
        __syncthreads();
        if (it + 1 < nIter) stage(s ^ 1, (it + 1) << 6);

        #pragma unroll
        for (int ks = 0; ks < 4; ks++) {
            uint32_t af0[4], af1[4];
            ldm_x4(af0[0], af0[1], af0[2], af0[3],
                   s2u(&As[s][aRow     ][ks*16 + aCol]));
            ldm_x4(af1[0], af1[1], af1[2], af1[3],
                   s2u(&As[s][aRow + 16][ks*16 + aCol]));
            #pragma unroll
            for (int tp = 0; tp < 4; tp++) {
                uint32_t b0, b1, b2, b3;
                ldm_x4(b0, b1, b2, b3,
                       s2u(&Bs[s][bRow + tp*16][ks*16 + bCol]));
                mma_f16(acc[0][2*tp  ], af0, b0, b1);
                mma_f16(acc[1][2*tp  ], af1, b0, b1);
                mma_f16(acc[0][2*tp+1], af0, b2, b3);
                mma_f16(acc[1][2*tp+1], af1, b2, b3);
            }
        }
    }

    // epilogue
    #pragma unroll
    for (int mt = 0; mt < 2; mt++) {
        #pragma unroll
        for (int nt = 0; nt < 8; nt++) {
            int row0 = rowBase + wm*32 + mt*16 + r;
            int col  = colBase + wn*64 + nt*8 + 2*c;
            float bi0 = bias[col], bi1 = bias[col+1];
            float v0 = acc[mt][nt][0] + bi0;
            float v1 = acc[mt][nt][1] + bi1;
            float v2 = acc[mt][nt][2] + bi0;
            float v3 = acc[mt][nt][3] + bi1;
            if (RELU) { v0=fmaxf(v0,0.f); v1=fmaxf(v1,0.f); v2=fmaxf(v2,0.f); v3=fmaxf(v3,0.f); }
            if (RES) {
                const float2 r0 = *(const float2*)(Rm + (size_t)row0*N + col);
                const float2 r1 = *(const float2*)(Rm + (size_t)(row0+8)*N + col);
                v0 += r0.x; v1 += r0.y; v2 += r1.x; v3 += r1.y;
            }
            if (OUTH) {
                __half* C = (__half*)Cout;
                *(__half2*)(C + (size_t)row0*N + col)     = __floats2half2_rn(v0, v1);
                *(__half2*)(C + (size_t)(row0+8)*N + col) = __floats2half2_rn(v2, v3);
            } else {
                float* C = (float*)Cout;
                *(float2*)(C + (size_t)row0*N + col)     = make_float2(v0, v1);
                *(float2*)(C + (size_t)(row0+8)*N + col) = make_float2(v2, v3);
            }
        }
    }
}

// ---------------- flash attention v2 (fp16, q-tile 128, cp.async) ----------
// 256 threads = 8 warps, each warp owns 16 query rows. K,V double-buffered.
// K,V staged natural [key][d]; PV B-fragments via ldmatrix.trans.
__global__ void __launch_bounds__(256, 2) flash_h(const __half* __restrict__ qkv,
                                                  __half* __restrict__ out)
{
    __shared__ __half Ks[2][64][72];
    __shared__ __half Vs[2][64][72];
    __shared__ __half Ps[128][72];

    const int tid  = threadIdx.x;
    const int lane = tid & 31;
    const int warp = tid >> 5;
    const int r = lane >> 2;
    const int c = lane & 3;
    const int j  = lane >> 3;
    const int rr = lane & 7;
    const int b = blockIdx.z, h = blockIdx.y;
    const int q0 = blockIdx.x * 128;

    // Q fragments (fp16 in gmem), scaled by 0.125 (exact)
    uint32_t qf[4][4];
    {
        const __half2 sc = __floats2half2_rn(0.125f, 0.125f);
        const __half* qp  = qkv + (size_t)(b*TT + q0 + warp*16 + r) * (3*CC) + h*HS;
        const __half* qp8 = qp + (size_t)8 * (3*CC);
        #pragma unroll
        for (int ks = 0; ks < 4; ks++) {
            const int k2 = ks*16 + 2*c;
            __half2 a0 = __hmul2(*(const __half2*)(qp  + k2    ), sc);
            __half2 a1 = __hmul2(*(const __half2*)(qp8 + k2    ), sc);
            __half2 a2 = __hmul2(*(const __half2*)(qp  + k2 + 8), sc);
            __half2 a3 = __hmul2(*(const __half2*)(qp8 + k2 + 8), sc);
            qf[ks][0] = *(uint32_t*)&a0;
            qf[ks][1] = *(uint32_t*)&a1;
            qf[ks][2] = *(uint32_t*)&a2;
            qf[ks][3] = *(uint32_t*)&a3;
        }
    }

    float oacc[8][4];
    #pragma unroll
    for (int nt = 0; nt < 8; nt++)
        #pragma unroll
        for (int i = 0; i < 4; i++) oacc[nt][i] = 0.f;
    float m0 = -1e30f, m1 = -1e30f, l0 = 0.f, l1 = 0.f;

    auto stage = [&](int buf, int s0) {
        #pragma unroll
        for (int p = 0; p < 2; p++) {
            int q = tid + p*256;
            int row = q >> 3, dc = (q & 7) * 8;
            cp16(&Ks[buf][row][dc],
                 qkv + (size_t)(b*TT + s0 + row)*(3*CC) + CC + h*HS + dc);
        }
        #pragma unroll
        for (int p = 0; p < 2; p++) {
            int q = tid + p*256;
            int row = q >> 3, dc = (q & 7) * 8;
            cp16(&Vs[buf][row][dc],
                 qkv + (size_t)(b*TT + s0 + row)*(3*CC) + 2*CC + h*HS + dc);
        }
        cp_commit();
    };

    const int nIter = TT / 64;
    stage(0, 0);

    for (int i = 0; i < nIter; i++) {
        const int buf = i & 1;
        cp_wait<0>();
        __syncthreads();
        if (i + 1 < nIter) stage(buf ^ 1, (i + 1) * 64);

        // ---- S = Q K^T  (warp: 16 x 64) ----
        float sa[8][4];
        #pragma unroll
        for (int nt = 0; nt < 8; nt++)
            #pragma unroll
            for (int q = 0; q < 4; q++) sa[nt][q] = 0.f;
        #pragma unroll
        for (int ks = 0; ks < 4; ks++) {       // d-groups of 16
            #pragma unroll
            for (int tp = 0; tp < 4; tp++) {   // key-groups of 16
                uint32_t b0, b1, b2, b3;
                ldm_x4(b0, b1, b2, b3,
                       s2u(&Ks[buf][tp*16 + (j>>1)*8 + rr][ks*16 + (j&1)*8]));
                mma_f16(sa[2*tp  ], qf[ks], b0, b1);
                mma_f16(sa[2*tp+1], qf[ks], b2, b3);
            }
        }

        // ---- online softmax ----
        float mx0 = -1e30f, mx1 = -1e30f;
        #pragma unroll
        for (int nt = 0; nt < 8; nt++) {
            mx0 = fmaxf(mx0, fmaxf(sa[nt][0], sa[nt][1]));
            mx1 = fmaxf(mx1, fmaxf(sa[nt][2], sa[nt][3]));
        }
        mx0 = fmaxf(mx0, __shfl_xor_sync(0xffffffff, mx0, 1));
        mx0 = fmaxf(mx0, __shfl_xor_sync(0xffffffff, mx0, 2));
        mx1 = fmaxf(mx1, __shfl_xor_sync(0xffffffff, mx1, 1));
        mx1 = fmaxf(mx1, __shfl_xor_sync(0xffffffff, mx1, 2));
        float mn0 = fmaxf(m0, mx0), mn1 = fmaxf(m1, mx1);
        float f0 = __expf(m0 - mn0), f1 = __expf(m1 - mn1);
        m0 = mn0; m1 = mn1;

        float ps0 = 0.f, ps1 = 0.f;
        const int prow = warp*16 + r;
        #pragma unroll
        for (int nt = 0; nt < 8; nt++) {
            float p0 = __expf(sa[nt][0] - mn0);
            float p1 = __expf(sa[nt][1] - mn0);
            float p2 = __expf(sa[nt][2] - mn1);
            float p3 = __expf(sa[nt][3] - mn1);
            ps0 += p0 + p1; ps1 += p2 + p3;
            *(__half2*)&Ps[prow    ][nt*8 + 2*c] = __floats2half2_rn(p0, p1);
            *(__half2*)&Ps[prow + 8][nt*8 + 2*c] = __floats2half2_rn(p2, p3);
        }
        ps0 += __shfl_xor_sync(0xffffffff, ps0, 1);
        ps0 += __shfl_xor_sync(0xffffffff, ps0, 2);
        ps1 += __shfl_xor_sync(0xffffffff, ps1, 1);
        ps1 += __shfl_xor_sync(0xffffffff, ps1, 2);
        l0 = l0 * f0 + ps0;
        l1 = l1 * f1 + ps1;

        #pragma unroll
        for (int nt = 0; nt < 8; nt++) {
            oacc[nt][0] *= f0; oacc[nt][1] *= f0;
            oacc[nt][2] *= f1; oacc[nt][3] *= f1;
        }
        __syncwarp();

        // ---- O += P V  (A = Ps via ldmatrix, B = natural V via ldmatrix.trans)
        #pragma unroll
        for (int ks = 0; ks < 4; ks++) {       // key-groups of 16
            uint32_t af[4];
            ldm_x4(af[0], af[1], af[2], af[3],
                   s2u(&Ps[warp*16 + (j&1)*8 + rr][ks*16 + (j>>1)*8]));
            #pragma unroll
            for (int tp = 0; tp < 4; tp++) {   // d-groups of 16
                uint32_t b0, b1, b2, b3;
                ldm_x4_t(b0, b1, b2, b3,
                         s2u(&Vs[buf][ks*16 + (j&1)*8 + rr][tp*16 + (j>>1)*8]));
                mma_f16(oacc[2*tp  ], af, b0, b1);
                mma_f16(oacc[2*tp+1], af, b2, b3);
            }
        }
        __syncwarp();
    }

    // write out fp16 (head-concat layout)
    float il0 = 1.f / l0, il1 = 1.f / l1;
    const int grow = b*TT + q0 + warp*16 + r;
    __half* op0 = out + (size_t)grow * CC + h*HS;
    __half* op1 = op0 + (size_t)8 * CC;
    #pragma unroll
    for (int nt = 0; nt < 8; nt++) {
        int col = nt*8 + 2*c;
        *(__half2*)(op0 + col) = __floats2half2_rn(oacc[nt][0]*il0, oacc[nt][1]*il0);
        *(__half2*)(op1 + col) = __floats2half2_rn(oacc[nt][2]*il1, oacc[nt][3]*il1);
    }
}

// ---------------- launch -----------------------------------------------
extern "C" void kernel_launch(void* const* d_in, const int* in_sizes, int n_in,
                              void* d_out, int out_size)
{
    const float* x      = (const float*)d_in[0];
    const float* Wq     = (const float*)d_in[1];
    const float* bq     = (const float*)d_in[2];
    const float* Wk     = (const float*)d_in[3];
    const float* bk     = (const float*)d_in[4];
    const float* Wv     = (const float*)d_in[5];
    const float* bv     = (const float*)d_in[6];
    const float* Wo     = (const float*)d_in[7];
    const float* bo     = (const float*)d_in[8];
    const float* W1     = (const float*)d_in[9];
    const float* b1     = (const float*)d_in[10];
    const float* W2     = (const float*)d_in[11];
    const float* b2     = (const float*)d_in[12];
    const float* gamma1 = (const float*)d_in[13];
    const float* beta1  = (const float*)d_in[14];
    const float* gamma2 = (const float*)d_in[15];
    const float* beta2  = (const float*)d_in[16];
    float* out = (float*)d_out;

    __half *p_h, *p_attn, *p_qkv, *p_wqkv, *p_mid, *p_wot, *p_w1t, *p_w2t;
    float *p_x1, *p_bqkv, *p_mean, *p_inv;
    cudaGetSymbolAddress((void**)&p_h,    g_h);
    cudaGetSymbolAddress((void**)&p_x1,   g_x1);
    cudaGetSymbolAddress((void**)&p_attn, g_attn);
    cudaGetSymbolAddress((void**)&p_qkv,  g_qkv);
    cudaGetSymbolAddress((void**)&p_wqkv, g_wqkv);
    cudaGetSymbolAddress((void**)&p_bqkv, g_bqkv);
    cudaGetSymbolAddress((void**)&p_mid,  g_mid);
    cudaGetSymbolAddress((void**)&p_mean, g_mean);
    cudaGetSymbolAddress((void**)&p_inv,  g_inv);
    cudaGetSymbolAddress((void**)&p_wot,  g_wot);
    cudaGetSymbolAddress((void**)&p_w1t,  g_w1t);
    cudaGetSymbolAddress((void**)&p_w2t,  g_w2t);

    dim3 lnb(32, 8);
    dim3 lng(CC/32, BB);
    const int elemBlocks = (MM*CC + 255)/256;
    dim3 tb(32, 8);

    // 0) weight prep
    transpose_h<<<dim3(32, 32),  tb>>>(Wo, p_wot, CC,   CC);
    transpose_h<<<dim3(32, 128), tb>>>(W1, p_w1t, CC,   4*CC);
    transpose_h<<<dim3(128, 32), tb>>>(W2, p_w2t, 4*CC, CC);
    pack_qkv_t<<<dim3(32, 96), tb>>>(Wq, Wk, Wv, p_wqkv);
    pack_bias<<<3, 1024>>>(bq, bk, bv, p_bqkv);

    // 1) LN1
    ln_stats<<<lng, lnb>>>(x, p_mean, p_inv);
    ln_apply<<<elemBlocks, 256>>>(x, p_mean, p_inv, gamma1, beta1, p_h);

    // 2) fused QKV GEMM -> g_qkv [4096, 3072] fp16
    h_gemm<false,false,true><<<dim3(3*CC/128, MM/128), 256>>>(
        p_h, p_wqkv, p_bqkv, nullptr, p_qkv, MM, 3*CC, CC);

    // 3) flash attention -> g_attn fp16
    flash_h<<<dim3(TT/128, HH, BB), 256>>>(p_qkv, p_attn);

    // 4) output projection + residual -> g_x1 (fp32)
    h_gemm<false,true,false><<<dim3(CC/128, MM/128), 256>>>(
        p_attn, p_wot, bo, x, p_x1, MM, CC, CC);

    // 5) LN2
    ln_stats<<<lng, lnb>>>(p_x1, p_mean, p_inv);
    ln_apply<<<elemBlocks, 256>>>(p_x1, p_mean, p_inv, gamma2, beta2, p_h);

    // 6) FFN
    h_gemm<true,false,true><<<dim3(4*CC/128, MM/128), 256>>>(
        p_h, p_w1t, b1, nullptr, p_mid, MM, 4*CC, CC);
    h_gemm<false,true,false><<<dim3(CC/128, MM/128), 256>>>(
        p_mid, p_w2t, b2, p_x1, out, MM, CC, 4*CC);
}

// round 10
// speedup vs baseline: 2.8597x; 1.0470x over previous
#include <cuda_runtime.h>
#include <cuda_fp16.h>
#include <math.h>
#include <stdint.h>

// Problem constants
#define BB 2
#define TT 2048
#define CC 1024
#define HH 16
#define HS 64
#define MM (BB*TT)          // 4096 rows
#define EPS 1e-5f

// ---------------- scratch (device globals; no runtime allocation) ----------
__device__ __align__(16) __half g_h   [MM*CC];      // LN output, fp16
__device__ float                g_x1  [MM*CC];      // after attention residual (fp32)
__device__ __align__(16) __half g_attn[MM*CC];      // attention output, fp16
__device__ __align__(16) __half g_qkv [MM*3*CC];    // q|k|v, fp16
__device__ __align__(16) __half g_wqkv[3*CC*CC];    // packed qkv weight [3C][C] K-major fp16
__device__ float                g_bqkv[3*CC];
__device__ __align__(16) __half g_mid [MM*4*CC];    // FFN hidden, fp16
__device__ __align__(16) __half g_wot [CC*CC];      // Wo^T  [C][C]   fp16
__device__ __align__(16) __half g_w1t [4*CC*CC];    // W1^T  [4C][C]  fp16
__device__ __align__(16) __half g_w2t [CC*4*CC];    // W2^T  [C][4C]  fp16
__device__ float                g_mean[BB*CC];
__device__ float                g_inv [BB*CC];
__device__ float                g_ps  [BB*8*CC];    // LN partial sums
__device__ float                g_pq  [BB*8*CC];    // LN partial sumsq

// ---------------- helpers ---------------------------------------------------
__device__ __forceinline__ void mma_f16(float c[4], const uint32_t a[4],
                                        uint32_t b0, uint32_t b1) {
    asm("mma.sync.aligned.m16n8k16.row.col.f32.f16.f16.f32 "
        "{%0,%1,%2,%3},{%4,%5,%6,%7},{%8,%9},{%0,%1,%2,%3};"
        : "+f"(c[0]), "+f"(c[1]), "+f"(c[2]), "+f"(c[3])
        : "r"(a[0]), "r"(a[1]), "r"(a[2]), "r"(a[3]), "r"(b0), "r"(b1));
}

__device__ __forceinline__ void ldm_x4(uint32_t& r0, uint32_t& r1,
                                       uint32_t& r2, uint32_t& r3, uint32_t addr) {
    asm volatile("ldmatrix.sync.aligned.m8n8.x4.shared.b16 {%0,%1,%2,%3}, [%4];"
        : "=r"(r0), "=r"(r1), "=r"(r2), "=r"(r3) : "r"(addr));
}
__device__ __forceinline__ void ldm_x4_t(uint32_t& r0, uint32_t& r1,
                                         uint32_t& r2, uint32_t& r3, uint32_t addr) {
    asm volatile("ldmatrix.sync.aligned.m8n8.x4.trans.shared.b16 {%0,%1,%2,%3}, [%4];"
        : "=r"(r0), "=r"(r1), "=r"(r2), "=r"(r3) : "r"(addr));
}

__device__ __forceinline__ void cp16(void* smem, const void* gmem) {
    uint32_t s = (uint32_t)__cvta_generic_to_shared(smem);
    asm volatile("cp.async.cg.shared.global [%0], [%1], 16;\n" :: "r"(s), "l"(gmem));
}
__device__ __forceinline__ void cp_commit() {
    asm volatile("cp.async.commit_group;\n");
}
template<int N>
__device__ __forceinline__ void cp_wait() {
    asm volatile("cp.async.wait_group %0;\n" :: "n"(N));
}
__device__ __forceinline__ uint32_t s2u(const void* p) {
    return (uint32_t)__cvta_generic_to_shared(p);
}

// ---------------- LayerNorm over axis=1 (sequence axis), split-T -----------
// grid (CC/32, 8, BB), block (32,8): each block reduces a 256-row T-chunk.
__global__ void ln_part(const float* __restrict__ x,
                        float* __restrict__ ps, float* __restrict__ pq)
{
    int c = blockIdx.x * 32 + threadIdx.x;
    int chunk = blockIdx.y;
    int b = blockIdx.z;
    int t0 = chunk * 256;
    float s = 0.f, ss = 0.f;
    #pragma unroll 4
    for (int t = t0 + threadIdx.y; t < t0 + 256; t += 8) {
        float v = x[((size_t)b*TT + t)*CC + c];
        s += v; ss += v*v;
    }
    __shared__ float sh_s[8][32];
    __shared__ float sh_q[8][32];
    sh_s[threadIdx.y][threadIdx.x] = s;
    sh_q[threadIdx.y][threadIdx.x] = ss;
    __syncthreads();
    if (threadIdx.y == 0) {
        #pragma unroll
        for (int i = 1; i < 8; i++) { s += sh_s[i][threadIdx.x]; ss += sh_q[i][threadIdx.x]; }
        ps[(size_t)(b*8 + chunk)*CC + c] = s;
        pq[(size_t)(b*8 + chunk)*CC + c] = ss;
    }
}

// finalize: 2048 threads, each sums 8 partials -> mean, inv
__global__ void ln_fin(const float* __restrict__ ps, const float* __restrict__ pq,
                       float* __restrict__ mean, float* __restrict__ inv)
{
    int idx = blockIdx.x * 256 + threadIdx.x;   // 0..BB*CC-1
    int b = idx >> 10;
    int c = idx & (CC-1);
    float s = 0.f, q = 0.f;
    #pragma unroll
    for (int k = 0; k < 8; k++) {
        s += ps[(size_t)(b*8 + k)*CC + c];
        q += pq[(size_t)(b*8 + k)*CC + c];
    }
    float mu  = s / (float)TT;
    float var = (q - s*mu) / (float)(TT - 1);   // unbiased
    mean[idx] = mu;
    inv [idx] = 1.f / (sqrtf(var) + EPS);       // eps OUTSIDE sqrt
}

__global__ void ln_apply(const float* __restrict__ x,
                         const float* __restrict__ mean, const float* __restrict__ inv,
                         const float* __restrict__ gamma, const float* __restrict__ beta,
                         __half* __restrict__ y)
{
    int idx = blockIdx.x * blockDim.x + threadIdx.x;
    if (idx >= MM*CC) return;
    int c  = idx & (CC-1);
    int bt = idx >> 10;
    int b  = bt >> 11;
    y[idx] = __float2half(gamma[c] * ((x[idx] - mean[b*CC + c]) * inv[b*CC + c]) + beta[c]);
}

// ---------------- weight transposes (to K-major [N][K], fp16) --------------
__global__ void transpose_h(const float* __restrict__ src, __half* __restrict__ dst,
                            int K, int N)
{
    __shared__ float t[32][33];
    int kb = blockIdx.x * 32, nb = blockIdx.y * 32;
    #pragma unroll
    for (int i = threadIdx.y; i < 32; i += 8)
        t[i][threadIdx.x] = src[(size_t)(kb + i)*N + nb + threadIdx.x];
    __syncthreads();
    #pragma unroll
    for (int i = threadIdx.y; i < 32; i += 8)
        dst[(size_t)(nb + i)*K + kb + threadIdx.x] = __float2half(t[threadIdx.x][i]);
}

__global__ void pack_qkv_t(const float* __restrict__ Wq, const float* __restrict__ Wk,
                           const float* __restrict__ Wv, __half* __restrict__ W)
{
    __shared__ float t[32][33];
    int z = blockIdx.y;
    int dt = z & 1;  z >>= 1;
    int h  = z & 15; z >>= 4;
    int sel = z;
    const float* src = (sel == 0) ? Wq : (sel == 1) ? Wk : Wv;
    int kb = blockIdx.x * 32, db = dt * 32;
    #pragma unroll
    for (int i = threadIdx.y; i < 32; i += 8)
        t[i][threadIdx.x] = src[((size_t)h*CC + kb + i)*HS + db + threadIdx.x];
    __syncthreads();
    #pragma unroll
    for (int i = threadIdx.y; i < 32; i += 8) {
        int n = sel*CC + h*HS + db + i;
        W[(size_t)n*CC + kb + threadIdx.x] = __float2half(t[threadIdx.x][i]);
    }
}

__global__ void pack_bias(const float* __restrict__ bq, const float* __restrict__ bk,
                          const float* __restrict__ bv, float* __restrict__ bias)
{
    int i = blockIdx.x * 1024 + threadIdx.x;
    const float* s = (i < CC) ? bq : (i < 2*CC) ? bk : bv;
    bias[i] = s[i & (CC-1)];
}

// ---------------- FP16 MMA GEMM, BK=64, 3-stage cp.async, ldmatrix ---------
// CTA tile 128x128, 8 warps (warp tile 32x64), m16n8k16, fp32 accum.
// Dynamic smem: [A0,A1,A2,B0,B1,B2], each stage 128x72 halves.
#define GA_STG (128*72)
#define G_SMEM (6*GA_STG*2)   // bytes = 110592
template<bool RELU, bool RES, bool OUTH>
__global__ void __launch_bounds__(256, 2) h_gemm(
    const __half* __restrict__ A, const __half* __restrict__ Bt,
    const float* __restrict__ bias, const float* __restrict__ Rm,
    void* __restrict__ Cout, int M, int N, int K)
{
    extern __shared__ __half sm[];

    const int tid  = threadIdx.x;
    const int lane = tid & 31;
    const int warp = tid >> 5;
    const int wm = warp & 3;
    const int wn = warp >> 2;
    const int r = lane >> 2;
    const int c = lane & 3;
    const int j  = lane >> 3;
    const int rr = lane & 7;
    const int rowBase = blockIdx.y * 128;
    const int colBase = blockIdx.x * 128;

    float acc[2][8][4];
    #pragma unroll
    for (int mt = 0; mt < 2; mt++)
        #pragma unroll
        for (int nt = 0; nt < 8; nt++)
            #pragma unroll
            for (int i = 0; i < 4; i++) acc[mt][nt][i] = 0.f;

    const __half* Ag = A  + (size_t)rowBase * K;
    const __half* Bg = Bt + (size_t)colBase * K;

    auto stage = [&](int s, int ch) {
        const int k0 = ch << 6;
        __half* Ab = sm + s*GA_STG;
        __half* Bb = sm + 3*GA_STG + s*GA_STG;
        #pragma unroll
        for (int p = 0; p < 4; p++) {
            int q = tid + p*256;
            int row = q >> 3, kc = (q & 7) * 8;
            cp16(Ab + row*72 + kc, Ag + (size_t)row * K + k0 + kc);
        }
        #pragma unroll
        for (int p = 0; p < 4; p++) {
            int q = tid + p*256;
            int row = q >> 3, kc = (q & 7) * 8;
            cp16(Bb + row*72 + kc, Bg + (size_t)row * K + k0 + kc);
        }
        cp_commit();
    };

    const int aRow = wm*32 + (j & 1)*8 + rr;
    const int aCol = (j >> 1) * 8;
    const int bRow = wn*64 + (j >> 1)*8 + rr;
    const int bCol = (j & 1) * 8;

    const int nIter = K >> 6;
    stage(0, 0);
    stage(1, 1);
    int s = 0;

    for (int it = 0; it < nIter; it++) {
        if (it + 1 < nIter) cp_wait<1>(); else cp_wait<0>();
        __syncthreads();
        if (it + 2 < nIter) {
            int sl = s + 2; if (sl >= 3) sl -= 3;
            stage(sl, it + 2);
        }

        const __half* Ab = sm + s*GA_STG;
        const __half* Bb = sm + 3*GA_STG + s*GA_STG;
        #pragma unroll
        for (int ks = 0; ks < 4; ks++) {
            uint32_t af0[4], af1[4];
            ldm_x4(af0[0], af0[1], af0[2], af0[3],
                   s2u(Ab + (aRow     )*72 + ks*16 + aCol));
            ldm_x4(af1[0], af1[1], af1[2], af1[3],
                   s2u(Ab + (aRow + 16)*72 + ks*16 + aCol));
            #pragma unroll
            for (int tp = 0; tp < 4; tp++) {
                uint32_t b0, b1, b2, b3;
                ldm_x4(b0, b1, b2, b3,
                       s2u(Bb + (bRow + tp*16)*72 + ks*16 + bCol));
                mma_f16(acc[0][2*tp  ], af0, b0, b1);
                mma_f16(acc[1][2*tp  ], af1, b0, b1);
                mma_f16(acc[0][2*tp+1], af0, b2, b3);
                mma_f16(acc[1][2*tp+1], af1, b2, b3);
            }
        }
        if (++s == 3) s = 0;
    }

    // epilogue
    #pragma unroll
    for (int mt = 0; mt < 2; mt++) {
        #pragma unroll
        for (int nt = 0; nt < 8; nt++) {
            int row0 = rowBase + wm*32 + mt*16 + r;
            int col  = colBase + wn*64 + nt*8 + 2*c;
            float bi0 = bias[col], bi1 = bias[col+1];
            float v0 = acc[mt][nt][0] + bi0;
            float v1 = acc[mt][nt][1] + bi1;
            float v2 = acc[mt][nt][2] + bi0;
            float v3 = acc[mt][nt][3] + bi1;
            if (RELU) { v0=fmaxf(v0,0.f); v1=fmaxf(v1,0.f); v2=fmaxf(v2,0.f); v3=fmaxf(v3,0.f); }
            if (RES) {
                const float2 r0 = *(const float2*)(Rm + (size_t)row0*N + col);
                const float2 r1 = *(const float2*)(Rm + (size_t)(row0+8)*N + col);
                v0 += r0.x; v1 += r0.y; v2 += r1.x; v3 += r1.y;
            }
            if (OUTH) {
                __half* C = (__half*)Cout;
                *(__half2*)(C + (size_t)row0*N + col)     = __floats2half2_rn(v0, v1);
                *(__half2*)(C + (size_t)(row0+8)*N + col) = __floats2half2_rn(v2, v3);
            } else {
                float* C = (float*)Cout;
                *(float2*)(C + (size_t)row0*N + col)     = make_float2(v0, v1);
                *(float2*)(C + (size_t)(row0+8)*N + col) = make_float2(v2, v3);
            }
        }
    }
}

// ---------------- flash attention v2 (fp16, q-tile 128, cp.async) ----------
__global__ void __launch_bounds__(256, 2) flash_h(const __half* __restrict__ qkv,
                                                  __half* __restrict__ out)
{
    __shared__ __half Ks[2][64][72];
    __shared__ __half Vs[2][64][72];
    __shared__ __half Ps[128][72];

    const int tid  = threadIdx.x;
    const int lane = tid & 31;
    const int warp = tid >> 5;
    const int r = lane >> 2;
    const int c = lane & 3;
    const int j  = lane >> 3;
    const int rr = lane & 7;
    const int b = blockIdx.z, h = blockIdx.y;
    const int q0 = blockIdx.x * 128;

    uint32_t qf[4][4];
    {
        const __half2 sc = __floats2half2_rn(0.125f, 0.125f);
        const __half* qp  = qkv + (size_t)(b*TT + q0 + warp*16 + r) * (3*CC) + h*HS;
        const __half* qp8 = qp + (size_t)8 * (3*CC);
        #pragma unroll
        for (int ks = 0; ks < 4; ks++) {
            const int k2 = ks*16 + 2*c;
            __half2 a0 = __hmul2(*(const __half2*)(qp  + k2    ), sc);
            __half2 a1 = __hmul2(*(const __half2*)(qp8 + k2    ), sc);
            __half2 a2 = __hmul2(*(const __half2*)(qp  + k2 + 8), sc);
            __half2 a3 = __hmul2(*(const __half2*)(qp8 + k2 + 8), sc);
            qf[ks][0] = *(uint32_t*)&a0;
            qf[ks][1] = *(uint32_t*)&a1;
            qf[ks][2] = *(uint32_t*)&a2;
            qf[ks][3] = *(uint32_t*)&a3;
        }
    }

    float oacc[8][4];
    #pragma unroll
    for (int nt = 0; nt < 8; nt++)
        #pragma unroll
        for (int i = 0; i < 4; i++) oacc[nt][i] = 0.f;
    float m0 = -1e30f, m1 = -1e30f, l0 = 0.f, l1 = 0.f;

    auto stage = [&](int buf, int s0) {
        #pragma unroll
        for (int p = 0; p < 2; p++) {
            int q = tid + p*256;
            int row = q >> 3, dc = (q & 7) * 8;
            cp16(&Ks[buf][row][dc],
                 qkv + (size_t)(b*TT + s0 + row)*(3*CC) + CC + h*HS + dc);
        }
        #pragma unroll
        for (int p = 0; p < 2; p++) {
            int q = tid + p*256;
            int row = q >> 3, dc = (q & 7) * 8;
            cp16(&Vs[buf][row][dc],
                 qkv + (size_t)(b*TT + s0 + row)*(3*CC) + 2*CC + h*HS + dc);
        }
        cp_commit();
    };

    const int nIter = TT / 64;
    stage(0, 0);

    for (int i = 0; i < nIter; i++) {
        const int buf = i & 1;
        cp_wait<0>();
        __syncthreads();
        if (i + 1 < nIter) stage(buf ^ 1, (i + 1) * 64);

        // ---- S = Q K^T ----
        float sa[8][4];
        #pragma unroll
        for (int nt = 0; nt < 8; nt++)
            #pragma unroll
            for (int q = 0; q < 4; q++) sa[nt][q] = 0.f;
        #pragma unroll
        for (int ks = 0; ks < 4; ks++) {
            #pragma unroll
            for (int tp = 0; tp < 4; tp++) {
                uint32_t b0, b1, b2, b3;
                ldm_x4(b0, b1, b2, b3,
                       s2u(&Ks[buf][tp*16 + (j>>1)*8 + rr][ks*16 + (j&1)*8]));
                mma_f16(sa[2*tp  ], qf[ks], b0, b1);
                mma_f16(sa[2*tp+1], qf[ks], b2, b3);
            }
        }

        // ---- online softmax ----
        float mx0 = -1e30f, mx1 = -1e30f;
        #pragma unroll
        for (int nt = 0; nt < 8; nt++) {
            mx0 = fmaxf(mx0, fmaxf(sa[nt][0], sa[nt][1]));
            mx1 = fmaxf(mx1, fmaxf(sa[nt][2], sa[nt][3]));
        }
        mx0 = fmaxf(mx0, __shfl_xor_sync(0xffffffff, mx0, 1));
        mx0 = fmaxf(mx0, __shfl_xor_sync(0xffffffff, mx0, 2));
        mx1 = fmaxf(mx1, __shfl_xor_sync(0xffffffff, mx1, 1));
        mx1 = fmaxf(mx1, __shfl_xor_sync(0xffffffff, mx1, 2));
        float mn0 = fmaxf(m0, mx0), mn1 = fmaxf(m1, mx1);
        float f0 = __expf(m0 - mn0), f1 = __expf(m1 - mn1);
        m0 = mn0; m1 = mn1;

        float ps0 = 0.f, ps1 = 0.f;
        const int prow = warp*16 + r;
        #pragma unroll
        for (int nt = 0; nt < 8; nt++) {
            float p0 = __expf(sa[nt][0] - mn0);
            float p1 = __expf(sa[nt][1] - mn0);
            float p2 = __expf(sa[nt][2] - mn1);
            float p3 = __expf(sa[nt][3] - mn1);
            ps0 += p0 + p1; ps1 += p2 + p3;
            *(__half2*)&Ps[prow    ][nt*8 + 2*c] = __floats2half2_rn(p0, p1);
            *(__half2*)&Ps[prow + 8][nt*8 + 2*c] = __floats2half2_rn(p2, p3);
        }
        ps0 += __shfl_xor_sync(0xffffffff, ps0, 1);
        ps0 += __shfl_xor_sync(0xffffffff, ps0, 2);
        ps1 += __shfl_xor_sync(0xffffffff, ps1, 1);
        ps1 += __shfl_xor_sync(0xffffffff, ps1, 2);
        l0 = l0 * f0 + ps0;
        l1 = l1 * f1 + ps1;

        #pragma unroll
        for (int nt = 0; nt < 8; nt++) {
            oacc[nt][0] *= f0; oacc[nt][1] *= f0;
            oacc[nt][2] *= f1; oacc[nt][3] *= f1;
        }
        __syncwarp();

        // ---- O += P V ----
        #pragma unroll
        for (int ks = 0; ks < 4; ks++) {
            uint32_t af[4];
            ldm_x4(af[0], af[1], af[2], af[3],
                   s2u(&Ps[warp*16 + (j&1)*8 + rr][ks*16 + (j>>1)*8]));
            #pragma unroll
            for (int tp = 0; tp < 4; tp++) {
                uint32_t b0, b1, b2, b3;
                ldm_x4_t(b0, b1, b2, b3,
                         s2u(&Vs[buf][ks*16 + (j&1)*8 + rr][tp*16 + (j>>1)*8]));
                mma_f16(oacc[2*tp  ], af, b0, b1);
                mma_f16(oacc[2*tp+1], af, b2, b3);
            }
        }
        __syncwarp();
    }

    float il0 = 1.f / l0, il1 = 1.f / l1;
    const int grow = b*TT + q0 + warp*16 + r;
    __half* op0 = out + (size_t)grow * CC + h*HS;
    __half* op1 = op0 + (size_t)8 * CC;
    #pragma unroll
    for (int nt = 0; nt < 8; nt++) {
        int col = nt*8 + 2*c;
        *(__half2*)(op0 + col) = __floats2half2_rn(oacc[nt][0]*il0, oacc[nt][1]*il0);
        *(__half2*)(op1 + col) = __floats2half2_rn(oacc[nt][2]*il1, oacc[nt][3]*il1);
    }
}

// ---------------- launch -----------------------------------------------
extern "C" void kernel_launch(void* const* d_in, const int* in_sizes, int n_in,
                              void* d_out, int out_size)
{
    const float* x      = (const float*)d_in[0];
    const float* Wq     = (const float*)d_in[1];
    const float* bq     = (const float*)d_in[2];
    const float* Wk     = (const float*)d_in[3];
    const float* bk     = (const float*)d_in[4];
    const float* Wv     = (const float*)d_in[5];
    const float* bv     = (const float*)d_in[6];
    const float* Wo     = (const float*)d_in[7];
    const float* bo     = (const float*)d_in[8];
    const float* W1     = (const float*)d_in[9];
    const float* b1     = (const float*)d_in[10];
    const float* W2     = (const float*)d_in[11];
    const float* b2     = (const float*)d_in[12];
    const float* gamma1 = (const float*)d_in[13];
    const float* beta1  = (const float*)d_in[14];
    const float* gamma2 = (const float*)d_in[15];
    const float* beta2  = (const float*)d_in[16];
    float* out = (float*)d_out;

    __half *p_h, *p_attn, *p_qkv, *p_wqkv, *p_mid, *p_wot, *p_w1t, *p_w2t;
    float *p_x1, *p_bqkv, *p_mean, *p_inv, *p_ps, *p_pq;
    cudaGetSymbolAddress((void**)&p_h,    g_h);
    cudaGetSymbolAddress((void**)&p_x1,   g_x1);
    cudaGetSymbolAddress((void**)&p_attn, g_attn);
    cudaGetSymbolAddress((void**)&p_qkv,  g_qkv);
    cudaGetSymbolAddress((void**)&p_wqkv, g_wqkv);
    cudaGetSymbolAddress((void**)&p_bqkv, g_bqkv);
    cudaGetSymbolAddress((void**)&p_mid,  g_mid);
    cudaGetSymbolAddress((void**)&p_mean, g_mean);
    cudaGetSymbolAddress((void**)&p_inv,  g_inv);
    cudaGetSymbolAddress((void**)&p_wot,  g_wot);
    cudaGetSymbolAddress((void**)&p_w1t,  g_w1t);
    cudaGetSymbolAddress((void**)&p_w2t,  g_w2t);
    cudaGetSymbolAddress((void**)&p_ps,   g_ps);
    cudaGetSymbolAddress((void**)&p_pq,   g_pq);

    cudaFuncSetAttribute(h_gemm<false,false,true>,
                         cudaFuncAttributeMaxDynamicSharedMemorySize, G_SMEM);
    cudaFuncSetAttribute(h_gemm<false,true,false>,
                         cudaFuncAttributeMaxDynamicSharedMemorySize, G_SMEM);
    cudaFuncSetAttribute(h_gemm<true,false,true>,
                         cudaFuncAttributeMaxDynamicSharedMemorySize, G_SMEM);

    dim3 lnpg(CC/32, 8, BB);
    dim3 lnb(32, 8);
    const int elemBlocks = (MM*CC + 255)/256;
    dim3 tb(32, 8);

    // 0) weight prep
    transpose_h<<<dim3(32, 32),  tb>>>(Wo, p_wot, CC,   CC);
    transpose_h<<<dim3(32, 128), tb>>>(W1, p_w1t, CC,   4*CC);
    transpose_h<<<dim3(128, 32), tb>>>(W2, p_w2t, 4*CC, CC);
    pack_qkv_t<<<dim3(32, 96), tb>>>(Wq, Wk, Wv, p_wqkv);
    pack_bias<<<3, 1024>>>(bq, bk, bv, p_bqkv);

    // 1) LN1
    ln_part<<<lnpg, lnb>>>(x, p_ps, p_pq);
    ln_fin<<<(BB*CC)/256, 256>>>(p_ps, p_pq, p_mean, p_inv);
    ln_apply<<<elemBlocks, 256>>>(x, p_mean, p_inv, gamma1, beta1, p_h);

    // 2) fused QKV GEMM -> g_qkv [4096, 3072] fp16
    h_gemm<false,false,true><<<dim3(3*CC/128, MM/128), 256, G_SMEM>>>(
        p_h, p_wqkv, p_bqkv, nullptr, p_qkv, MM, 3*CC, CC);

    // 3) flash attention -> g_attn fp16
    flash_h<<<dim3(TT/128, HH, BB), 256>>>(p_qkv, p_attn);

    // 4) output projection + residual -> g_x1 (fp32)
    h_gemm<false,true,false><<<dim3(CC/128, MM/128), 256, G_SMEM>>>(
        p_attn, p_wot, bo, x, p_x1, MM, CC, CC);

    // 5) LN2
    ln_part<<<lnpg, lnb>>>(p_x1, p_ps, p_pq);
    ln_fin<<<(BB*CC)/256, 256>>>(p_ps, p_pq, p_mean, p_inv);
    ln_apply<<<elemBlocks, 256>>>(p_x1, p_mean, p_inv, gamma2, beta2, p_h);

    // 6) FFN
    h_gemm<true,false,true><<<dim3(4*CC/128, MM/128), 256, G_SMEM>>>(
        p_h, p_w1t, b1, nullptr, p_mid, MM, 4*CC, CC);
    h_gemm<false,true,false><<<dim3(CC/128, MM/128), 256, G_SMEM>>>(
        p_mid, p_w2t, b2, p_x1, out, MM, CC, 4*CC);
}